// round 12
// baseline (speedup 1.0000x reference)
#include <cuda_runtime.h>
#include <cstdint>

// ---------------- problem constants ----------------
constexpr int B    = 8;
constexpr int L    = 512;
constexpr int HID  = 1024;
constexpr int H    = 16;
constexpr int HD   = 64;     // head dim
constexpr int TAB  = 129;    // 2*64+1 relative-position table rows
constexpr int BL   = B * L;  // 4096

// ---------------- device scratch ----------------
__device__ float g_Q[BL * HID];
__device__ float g_K[BL * HID];
__device__ float g_V[BL * HID];
__device__ float g_X[BL * HID];                 // w1+w2 merged
__device__ unsigned char g_fmb[(size_t)B * L * L];  // final_mat as uchar (2 MB)
__device__ float g_tk[136 * 68];                // table_k tf32-rounded, padded
__device__ float g_tv[136 * 72];                // table_v tf32-rounded, padded

// =====================================================================
// tf32 helpers
// =====================================================================
__device__ __forceinline__ float tf32r(float x) {
    unsigned y;
    asm("cvt.rna.tf32.f32 %0, %1;" : "=r"(y) : "f"(x));
    return __uint_as_float(y);
}

__device__ __forceinline__ float4 tf32r4(float4 v) {
    return make_float4(tf32r(v.x), tf32r(v.y), tf32r(v.z), tf32r(v.w));
}

__device__ __forceinline__ void mma_tf32(float d[4], const float a[4], const float b[2]) {
    unsigned const* A = reinterpret_cast<unsigned const*>(a);
    unsigned const* Bp = reinterpret_cast<unsigned const*>(b);
    asm volatile(
        "mma.sync.aligned.m16n8k8.row.col.f32.tf32.tf32.f32 "
        "{%0,%1,%2,%3}, {%4,%5,%6,%7}, {%8,%9}, {%0,%1,%2,%3};"
        : "+f"(d[0]), "+f"(d[1]), "+f"(d[2]), "+f"(d[3])
        : "r"(A[0]), "r"(A[1]), "r"(A[2]), "r"(A[3]),
          "r"(Bp[0]), "r"(Bp[1]));
}

// ---------------- cp.async helpers ----------------
__device__ __forceinline__ uint32_t smem_u32(const void* p) {
    uint32_t a;
    asm("{ .reg .u64 t; cvta.to.shared.u64 t, %1; cvt.u32.u64 %0, t; }"
        : "=r"(a) : "l"(p));
    return a;
}
#define CP_ASYNC16(dst, src) \
    asm volatile("cp.async.cg.shared.global [%0], [%1], 16;" \
                 :: "r"(dst), "l"(src) : "memory")
#define CP_COMMIT() asm volatile("cp.async.commit_group;" ::: "memory")
#define CP_WAIT0()  asm volatile("cp.async.wait_group 0;" ::: "memory")
#define CP_WAIT1()  asm volatile("cp.async.wait_group 1;" ::: "memory")

// =====================================================================
// Prep kernel: pack final_mat -> uchar; round+pad tables.
// =====================================================================
__global__ __launch_bounds__(256) void prep_kernel(
    const int* __restrict__ fm,
    const float* __restrict__ tk, const float* __restrict__ tv)
{
    if (blockIdx.x < 2048) {
        const int idx = blockIdx.x * 1024 + threadIdx.x * 4;
        const int4 v = *reinterpret_cast<const int4*>(fm + idx);
        *reinterpret_cast<uchar4*>(g_fmb + idx) =
            make_uchar4((unsigned char)v.x, (unsigned char)v.y,
                        (unsigned char)v.z, (unsigned char)v.w);
    } else {
        for (int i = threadIdx.x; i < 136 * 68; i += 256) {
            const int r = i / 68, c = i - r * 68;
            g_tk[i] = (r < TAB && c < 64) ? tf32r(tk[r * 64 + c]) : 0.f;
        }
        for (int i = threadIdx.x; i < 136 * 72; i += 256) {
            const int r = i / 72, c = i - r * 72;
            g_tv[i] = (r < TAB && c < 64) ? tf32r(tv[r * 64 + c]) : 0.f;
        }
    }
}

// =====================================================================
// GEMM v3 (R9): C[4096,1024] = A @ W^T + bias. 128x256x16 tiles, 512 thr,
// 16 warps (4m x 4n), warp tile 32x64, double-buffered smem.
// =====================================================================
constexpr int BKS = 20;
constexpr int GA  = 128 * BKS;
constexpr int GB  = 256 * BKS;
constexpr size_t GEMM_SMEM = (size_t)2 * (GA + GB) * 4;  // 61,440 B

template <bool ROUND>
__device__ __forceinline__ void gemm_body(
    const float* __restrict__ A, const float* __restrict__ W,
    const float* __restrict__ bias, float* __restrict__ C)
{
    extern __shared__ float dsm[];
    float* AsBase = dsm;
    float* BsBase = dsm + 2 * GA;

    const int tid  = threadIdx.x;
    const int m0   = blockIdx.y * 128;
    const int n0   = blockIdx.x * 256;
    const int lane = tid & 31;
    const int g    = lane >> 2;
    const int t    = lane & 3;
    const int warp = tid >> 5;
    const int wm   = warp >> 2;
    const int wn   = warp & 3;

    const int lr = tid >> 2;
    const int lc = (tid & 3) * 4;
    const float* Ap  = A + (size_t)(m0 + lr) * HID + lc;
    const float* Wp0 = W + (size_t)(n0 + lr) * HID + lc;
    const float* Wp1 = W + (size_t)(n0 + lr + 128) * HID + lc;

    float acc[2][8][4];
#pragma unroll
    for (int i = 0; i < 2; i++)
#pragma unroll
        for (int j = 0; j < 8; j++)
#pragma unroll
            for (int r = 0; r < 4; r++) acc[i][j][r] = 0.f;

    float4 pa, pb0, pb1;
    pa  = *reinterpret_cast<const float4*>(Ap);
    pb0 = *reinterpret_cast<const float4*>(Wp0);
    pb1 = *reinterpret_cast<const float4*>(Wp1);

    *reinterpret_cast<float4*>(AsBase + lr * BKS + lc) = tf32r4(pa);
    *reinterpret_cast<float4*>(BsBase + lr * BKS + lc) = tf32r4(pb0);
    *reinterpret_cast<float4*>(BsBase + (lr + 128) * BKS + lc) = tf32r4(pb1);

    int buf = 0;
    for (int k0 = 0; k0 < HID; k0 += 16, buf ^= 1) {
        __syncthreads();

        const bool more = (k0 + 16 < HID);
        if (more) {
            pa  = *reinterpret_cast<const float4*>(Ap  + k0 + 16);
            pb0 = *reinterpret_cast<const float4*>(Wp0 + k0 + 16);
            pb1 = *reinterpret_cast<const float4*>(Wp1 + k0 + 16);
        }

        const float* As = AsBase + buf * GA;
        const float* Bs = BsBase + buf * GB;
#pragma unroll
        for (int ks = 0; ks < 2; ks++) {
            const int kc = ks * 8 + t;
            float afr[2][4], bfr[8][2];
#pragma unroll
            for (int mt = 0; mt < 2; mt++) {
                const int r = wm * 32 + mt * 16 + g;
                afr[mt][0] = As[(r    ) * BKS + kc];
                afr[mt][1] = As[(r + 8) * BKS + kc];
                afr[mt][2] = As[(r    ) * BKS + kc + 4];
                afr[mt][3] = As[(r + 8) * BKS + kc + 4];
            }
#pragma unroll
            for (int nt = 0; nt < 8; nt++) {
                const int n = wn * 64 + nt * 8 + g;
                bfr[nt][0] = Bs[n * BKS + kc];
                bfr[nt][1] = Bs[n * BKS + kc + 4];
            }
#pragma unroll
            for (int mt = 0; mt < 2; mt++)
#pragma unroll
                for (int nt = 0; nt < 8; nt++)
                    mma_tf32(acc[mt][nt], afr[mt], bfr[nt]);
        }

        if (more) {
            float* asd = AsBase + (buf ^ 1) * GA;
            float* bsd = BsBase + (buf ^ 1) * GB;
            *reinterpret_cast<float4*>(asd + lr * BKS + lc) = tf32r4(pa);
            *reinterpret_cast<float4*>(bsd + lr * BKS + lc) = tf32r4(pb0);
            *reinterpret_cast<float4*>(bsd + (lr + 128) * BKS + lc) = tf32r4(pb1);
        }
    }

#pragma unroll
    for (int mt = 0; mt < 2; mt++) {
        const int row0 = m0 + wm * 32 + mt * 16 + g;
#pragma unroll
        for (int nt = 0; nt < 8; nt++) {
            const int col = n0 + wn * 64 + nt * 8 + 2 * t;
            const float b0 = bias[col], b1 = bias[col + 1];
            float* c0 = C + (size_t)row0 * HID + col;
            float* c1 = C + (size_t)(row0 + 8) * HID + col;
            if (ROUND) {
                c0[0] = tf32r(acc[mt][nt][0] + b0); c0[1] = tf32r(acc[mt][nt][1] + b1);
                c1[0] = tf32r(acc[mt][nt][2] + b0); c1[1] = tf32r(acc[mt][nt][3] + b1);
            } else {
                c0[0] = acc[mt][nt][0] + b0; c0[1] = acc[mt][nt][1] + b1;
                c1[0] = acc[mt][nt][2] + b0; c1[1] = acc[mt][nt][3] + b1;
            }
        }
    }
}

__global__ __launch_bounds__(512, 1) void gemm_qkv(
    const float* __restrict__ q_in, const float* __restrict__ k_in,
    const float* __restrict__ v_in,
    const float* __restrict__ Wq, const float* __restrict__ bq,
    const float* __restrict__ Wk, const float* __restrict__ bk,
    const float* __restrict__ Wv, const float* __restrict__ bv)
{
    if (blockIdx.z == 0)      gemm_body<true>(q_in, Wq, bq, g_Q);
    else if (blockIdx.z == 1) gemm_body<true>(k_in, Wk, bk, g_K);
    else                      gemm_body<true>(v_in, Wv, bv, g_V);
}

__global__ __launch_bounds__(512, 1) void gemm_out(
    const float* __restrict__ W, const float* __restrict__ bias,
    float* __restrict__ C)
{
    gemm_body<false>(g_X, W, bias, C);
}

// =====================================================================
// Fused MMA attention v6: cp.async staging + ATOMIC-FREE private-copy
// bucket scatter. block = (32 q, h, b), 512 threads, 16 warps.
//
// SMEM (float offsets):
//  sQ  @ 0      [32][68]            (union w/ sSb [32][136])
//  sP  @ 2176   [32][132]
//  sKV @ 6400   18432 floats: table_k[136][68] -> K dbuf 2x[128][68]
//               -> V dbuf 2x[128][72] -> scatter copies [4][32][136]
//  sS  @ 24832  [32][516] scores/attn -> table_v [136][72] (after scatter)
//  sF  @ 41344  [32] rows x 528 bytes (uchar)
// =====================================================================
constexpr int OFF_P  = 2176;
constexpr int OFF_KV = 6400;
constexpr int OFF_S  = 24832;
constexpr int OFF_F  = 41344;
constexpr int SMF_TOTAL = OFF_F + (32 * 528) / 4;       // 45568 floats
constexpr size_t SMF_BYTES = (size_t)SMF_TOTAL * 4;     // 182,272 B

__global__ __launch_bounds__(512) void attn_fused_mma()
{
    extern __shared__ float smem[];
    float* sQ  = smem;                 // [32][68]
    float* sP  = smem + OFF_P;         // [32][132]
    float* sSb = smem;                 // [32][136] union (reduction target)
    float* sKV = smem + OFF_KV;
    float* sS  = smem + OFF_S;         // [32][516]; later table_v [136][72]
    unsigned char* sFb = reinterpret_cast<unsigned char*>(smem + OFF_F);

    const uint32_t sbase = smem_u32(smem);
    const uint32_t sQa  = sbase;
    const uint32_t sKVa = sbase + OFF_KV * 4;
    const uint32_t sSa  = sbase + OFF_S * 4;
    const uint32_t sFa  = sbase + OFF_F * 4;

    const int tid  = threadIdx.x;
    const int lane = tid & 31;
    const int warp = tid >> 5;
    const int g    = lane >> 2;
    const int t    = lane & 3;
    const int mh   = warp >> 3;        // 0..1
    const int wg   = warp & 7;         // 0..7
    const int mr   = mh * 16;
    const int q0   = blockIdx.x * 32;
    const int h    = blockIdx.y;
    const int b    = blockIdx.z;

    const float* gKb = g_K + (size_t)(b * L) * HID + h * HD;
    const float* gVb = g_V + (size_t)(b * L) * HID + h * HD;

    // ---------- stage 0: cp.async Q, table_k, fm ----------
    {
        const int q = tid >> 4, seg = tid & 15;
        CP_ASYNC16(sQa + (uint32_t)(q * 68 + seg * 4) * 4,
                   g_Q + (size_t)(b * L + q0 + q) * HID + h * HD + seg * 4);
    }
    for (int i = tid; i < (136 * 68) / 4; i += 512)
        CP_ASYNC16(sKVa + (uint32_t)i * 16, g_tk + i * 4);
    for (int i = tid; i < 32 * 32; i += 512) {
        const int q = i >> 5, seg = i & 31;
        CP_ASYNC16(sFa + (uint32_t)(q * 528 + seg * 16),
                   g_fmb + (size_t)(b * L + q0 + q) * L + seg * 16);
    }
    CP_COMMIT();
    CP_WAIT0();
    __syncthreads();

    // ---------- Q fragments into registers ----------
    float qf[8][4];
#pragma unroll
    for (int ks = 0; ks < 8; ks++) {
        const int kb = ks * 8;
        qf[ks][0] = sQ[(mr + g    ) * 68 + kb + t];
        qf[ks][1] = sQ[(mr + g + 8) * 68 + kb + t];
        qf[ks][2] = sQ[(mr + g    ) * 68 + kb + t + 4];
        qf[ks][3] = sQ[(mr + g + 8) * 68 + kb + t + 4];
    }

    // ---------- P[32][129] = Q @ table_k^T ----------
#pragma unroll
    for (int j = 0; j < 3; j++) {
        const int n8 = wg + 8 * j;
        if (n8 > 16) break;
        const int nb = n8 * 8;
        float acc[4] = {0.f, 0.f, 0.f, 0.f};
#pragma unroll
        for (int ks = 0; ks < 8; ks++) {
            const int kb = ks * 8;
            float bb[2];
            bb[0] = sKV[(nb + g) * 68 + kb + t];
            bb[1] = sKV[(nb + g) * 68 + kb + t + 4];
            mma_tf32(acc, qf[ks], bb);
        }
        const int c0 = nb + 2 * t;
        if (c0 < TAB) {
            sP[(mr + g    ) * 132 + c0] = acc[0];
            sP[(mr + g + 8) * 132 + c0] = acc[2];
        }
        if (c0 + 1 < TAB) {
            sP[(mr + g    ) * 132 + c0 + 1] = acc[1];
            sP[(mr + g + 8) * 132 + c0 + 1] = acc[3];
        }
    }
    __syncthreads();   // table_k reads complete

    // ---------- issue K tile 0 ----------
#pragma unroll
    for (int j = 0; j < 4; j++) {
        const int idx = tid + 512 * j, row = idx >> 4, seg = idx & 15;
        CP_ASYNC16(sKVa + (uint32_t)(row * 68 + seg * 4) * 4,
                   gKb + (size_t)row * HID + seg * 4);
    }
    CP_COMMIT();

    // ---------- scores: 4 K-tiles of 128, double-buffered ----------
#pragma unroll 1
    for (int kt = 0; kt < 4; kt++) {
        if (kt < 3) {
            const uint32_t dstb = sKVa + (uint32_t)(((kt + 1) & 1) * 8704) * 4;
#pragma unroll
            for (int j = 0; j < 4; j++) {
                const int idx = tid + 512 * j, row = idx >> 4, seg = idx & 15;
                CP_ASYNC16(dstb + (uint32_t)(row * 68 + seg * 4) * 4,
                           gKb + (size_t)((kt + 1) * 128 + row) * HID + seg * 4);
            }
            CP_COMMIT();
            CP_WAIT1();
        } else {
            CP_WAIT0();
        }
        __syncthreads();

        const float* Kb = sKV + (kt & 1) * 8704;
#pragma unroll
        for (int jj = 0; jj < 2; jj++) {
            const int nb = (wg * 2 + jj) * 8;
            float acc[4] = {0.f, 0.f, 0.f, 0.f};
#pragma unroll
            for (int ks = 0; ks < 8; ks++) {
                const int kb = ks * 8;
                float bb[2];
                bb[0] = Kb[(nb + g) * 68 + kb + t];
                bb[1] = Kb[(nb + g) * 68 + kb + t + 4];
                mma_tf32(acc, qf[ks], bb);
            }
            const int row0 = mr + g, row1 = row0 + 8;
            const int kc = kt * 128 + nb + 2 * t;
            const int t00 = sFb[row0 * 528 + kc], t01 = sFb[row0 * 528 + kc + 1];
            const int t10 = sFb[row1 * 528 + kc], t11 = sFb[row1 * 528 + kc + 1];
            sS[row0 * 516 + kc    ] = (acc[0] + sP[row0 * 132 + t00]) * 0.125f;
            sS[row0 * 516 + kc + 1] = (acc[1] + sP[row0 * 132 + t01]) * 0.125f;
            sS[row1 * 516 + kc    ] = (acc[2] + sP[row1 * 132 + t10]) * 0.125f;
            sS[row1 * 516 + kc + 1] = (acc[3] + sP[row1 * 132 + t11]) * 0.125f;
        }
        __syncthreads();
    }

    // ---------- issue V tile 0 (hides under softmax) ----------
#pragma unroll
    for (int j = 0; j < 4; j++) {
        const int idx = tid + 512 * j, row = idx >> 4, seg = idx & 15;
        CP_ASYNC16(sKVa + (uint32_t)(row * 72 + seg * 4) * 4,
                   gVb + (size_t)row * HID + seg * 4);
    }
    CP_COMMIT();

    // ---------- softmax (16 warps x 2 rows) ----------
    for (int r = warp * 2; r < warp * 2 + 2; r++) {
        float* row = sS + r * 516;
        float m = -1e30f;
#pragma unroll
        for (int i = 0; i < 16; i++) m = fmaxf(m, row[lane + 32 * i]);
#pragma unroll
        for (int o = 16; o > 0; o >>= 1) m = fmaxf(m, __shfl_xor_sync(0xffffffffu, m, o));
        float e[16];
        float s = 0.f;
#pragma unroll
        for (int i = 0; i < 16; i++) {
            e[i] = __expf(row[lane + 32 * i] - m);
            s += e[i];
        }
#pragma unroll
        for (int o = 16; o > 0; o >>= 1) s += __shfl_xor_sync(0xffffffffu, s, o);
        const float inv = 1.f / s;
#pragma unroll
        for (int i = 0; i < 16; i++) row[lane + 32 * i] = tf32r(e[i] * inv);
    }
    CP_WAIT0();
    __syncthreads();

    // ---------- w1 = attn @ V: 4 V-tiles of 128, double-buffered ----------
    const int nbw = wg * 8;
    float acc1a[4] = {0.f, 0.f, 0.f, 0.f};
    float acc1b[4] = {0.f, 0.f, 0.f, 0.f};
#pragma unroll 1
    for (int vt = 0; vt < 4; vt++) {
        if (vt < 3) {
            const uint32_t dstb = sKVa + (uint32_t)(((vt + 1) & 1) * 9216) * 4;
#pragma unroll
            for (int j = 0; j < 4; j++) {
                const int idx = tid + 512 * j, row = idx >> 4, seg = idx & 15;
                CP_ASYNC16(dstb + (uint32_t)(row * 72 + seg * 4) * 4,
                           gVb + (size_t)((vt + 1) * 128 + row) * HID + seg * 4);
            }
            CP_COMMIT();
            CP_WAIT1();
        } else {
            CP_WAIT0();
        }
        __syncthreads();

        const float* Vb = sKV + (vt & 1) * 9216;
        const int cb = vt * 128;
#pragma unroll
        for (int ks = 0; ks < 16; ks += 2) {
            {
                const int kb = ks * 8;
                float a[4], bb[2];
                a[0] = sS[(mr + g    ) * 516 + cb + kb + t];
                a[1] = sS[(mr + g + 8) * 516 + cb + kb + t];
                a[2] = sS[(mr + g    ) * 516 + cb + kb + t + 4];
                a[3] = sS[(mr + g + 8) * 516 + cb + kb + t + 4];
                bb[0] = Vb[(kb + t    ) * 72 + nbw + g];
                bb[1] = Vb[(kb + t + 4) * 72 + nbw + g];
                mma_tf32(acc1a, a, bb);
            }
            {
                const int kb = (ks + 1) * 8;
                float a[4], bb[2];
                a[0] = sS[(mr + g    ) * 516 + cb + kb + t];
                a[1] = sS[(mr + g + 8) * 516 + cb + kb + t];
                a[2] = sS[(mr + g    ) * 516 + cb + kb + t + 4];
                a[3] = sS[(mr + g + 8) * 516 + cb + kb + t + 4];
                bb[0] = Vb[(kb + t    ) * 72 + nbw + g];
                bb[1] = Vb[(kb + t + 4) * 72 + nbw + g];
                mma_tf32(acc1b, a, bb);
            }
        }
        __syncthreads();
    }

    // ---------- ATOMIC-FREE scatter: 4 private copies in dead sKV ----------
    // sC layout: [c][q][136], c = k mod 4; 4*32*136 = 17408 floats <= 18432
    float* sC = sKV;
    for (int i = tid; i < (4 * 32 * 136) / 4; i += 512)
        *reinterpret_cast<float4*>(sC + i * 4) = make_float4(0.f, 0.f, 0.f, 0.f);
    __syncthreads();

    if (tid < 128) {
        const int q = tid >> 2;        // 0..31
        const int c = tid & 3;         // k mod 4
        const unsigned char* fr = sFb + q * 528;
        const float* ar = sS + q * 516;
        float* dst = sC + (c * 32 + q) * 136;
#pragma unroll 4
        for (int i = 0; i < 128; i++) {
            const int k = i * 4 + c;
            dst[fr[k]] += ar[k];
        }
    }
    __syncthreads();   // scatter done; sS (attn) now dead

    // ---------- issue table_v into sS region; reduce copies meanwhile ----------
    for (int i = tid; i < (136 * 72) / 4; i += 512)
        CP_ASYNC16(sSa + (uint32_t)i * 16, g_tv + i * 4);
    CP_COMMIT();

    for (int i = tid; i < 32 * 136; i += 512) {
        const int q = i / 136, tt = i - q * 136;
        sSb[i] = (sC[(0 * 32 + q) * 136 + tt] + sC[(1 * 32 + q) * 136 + tt])
               + (sC[(2 * 32 + q) * 136 + tt] + sC[(3 * 32 + q) * 136 + tt]);
    }
    CP_WAIT0();
    __syncthreads();

    // ---------- w2 = buckets @ table_v (17 k-steps, dual accumulators) ----------
    const float* tvS = sS;   // table_v [136][72] now lives here
    float acc2a[4] = {0.f, 0.f, 0.f, 0.f};
    float acc2b[4] = {0.f, 0.f, 0.f, 0.f};
#pragma unroll
    for (int ks = 0; ks < 17; ks++) {
        const int kb = ks * 8;
        float a[4], bb[2];
        a[0] = tf32r(sSb[(mr + g    ) * 136 + kb + t]);
        a[1] = tf32r(sSb[(mr + g + 8) * 136 + kb + t]);
        a[2] = tf32r(sSb[(mr + g    ) * 136 + kb + t + 4]);
        a[3] = tf32r(sSb[(mr + g + 8) * 136 + kb + t + 4]);
        bb[0] = tvS[(kb + t    ) * 72 + nbw + g];
        bb[1] = tvS[(kb + t + 4) * 72 + nbw + g];
        if (ks & 1) mma_tf32(acc2b, a, bb);
        else        mma_tf32(acc2a, a, bb);
    }

    // ---------- store ----------
    {
        const int row0 = mr + g;
        const int col  = nbw + 2 * t;
        float2 o0 = make_float2(acc1a[0] + acc1b[0] + acc2a[0] + acc2b[0],
                                acc1a[1] + acc1b[1] + acc2a[1] + acc2b[1]);
        float2 o1 = make_float2(acc1a[2] + acc1b[2] + acc2a[2] + acc2b[2],
                                acc1a[3] + acc1b[3] + acc2a[3] + acc2b[3]);
        *reinterpret_cast<float2*>(
            g_X + (size_t)(b * L + q0 + row0) * HID + h * HD + col) = o0;
        *reinterpret_cast<float2*>(
            g_X + (size_t)(b * L + q0 + row0 + 8) * HID + h * HD + col) = o1;
    }
}

// =====================================================================
// launch
// =====================================================================
extern "C" void kernel_launch(void* const* d_in, const int* in_sizes, int n_in,
                              void* d_out, int out_size)
{
    const float* query   = (const float*)d_in[0];
    const float* key     = (const float*)d_in[1];
    const float* value   = (const float*)d_in[2];
    const int*   fm      = (const int*)  d_in[3];
    const float* Wq      = (const float*)d_in[4];
    const float* bq      = (const float*)d_in[5];
    const float* Wk      = (const float*)d_in[6];
    const float* bk      = (const float*)d_in[7];
    const float* Wv      = (const float*)d_in[8];
    const float* bv      = (const float*)d_in[9];
    const float* Wo      = (const float*)d_in[10];
    const float* bo      = (const float*)d_in[11];
    const float* table_k = (const float*)d_in[12];
    const float* table_v = (const float*)d_in[13];
    float* out = (float*)d_out;

    cudaFuncSetAttribute(attn_fused_mma,
                         cudaFuncAttributeMaxDynamicSharedMemorySize, (int)SMF_BYTES);
    cudaFuncSetAttribute(gemm_qkv,
                         cudaFuncAttributeMaxDynamicSharedMemorySize, (int)GEMM_SMEM);
    cudaFuncSetAttribute(gemm_out,
                         cudaFuncAttributeMaxDynamicSharedMemorySize, (int)GEMM_SMEM);

    prep_kernel<<<2049, 256>>>(fm, table_k, table_v);

    const dim3 gqkv(HID / 256, BL / 128, 3);  // (4, 32, 3)
    gemm_qkv<<<gqkv, 512, GEMM_SMEM>>>(query, key, value, Wq, bq, Wk, bk, Wv, bv);

    const dim3 gattn(L / 32, H, B);  // (16, 16, 8)
    attn_fused_mma<<<gattn, 512, SMF_BYTES>>>();

    const dim3 gout(HID / 256, BL / 128);  // (4, 32)
    gemm_out<<<gout, 512, GEMM_SMEM>>>(Wo, bo, out);
}

// round 13
// speedup vs baseline: 1.0102x; 1.0102x over previous
#include <cuda_runtime.h>
#include <cstdint>

// ---------------- problem constants ----------------
constexpr int B    = 8;
constexpr int L    = 512;
constexpr int HID  = 1024;
constexpr int H    = 16;
constexpr int HD   = 64;     // head dim
constexpr int TAB  = 129;    // 2*64+1 relative-position table rows
constexpr int BL   = B * L;  // 4096

// ---------------- device scratch ----------------
__device__ float g_Q[BL * HID];
__device__ float g_K[BL * HID];
__device__ float g_V[BL * HID];
__device__ float g_X[BL * HID];                 // w1+w2 merged (tf32-rounded)
__device__ float g_rW[4 * HID * HID];           // pre-rounded Wq,Wk,Wv,Wo (16.8MB)
__device__ unsigned char g_fmb[(size_t)B * L * L];  // final_mat as uchar (2 MB)
__device__ float g_tk[136 * 68];                // table_k tf32-rounded, padded
__device__ float g_tv[136 * 72];                // table_v tf32-rounded, padded

// =====================================================================
// tf32 helpers
// =====================================================================
__device__ __forceinline__ float tf32r(float x) {
    unsigned y;
    asm("cvt.rna.tf32.f32 %0, %1;" : "=r"(y) : "f"(x));
    return __uint_as_float(y);
}

__device__ __forceinline__ float4 tf32r4(float4 v) {
    return make_float4(tf32r(v.x), tf32r(v.y), tf32r(v.z), tf32r(v.w));
}

__device__ __forceinline__ void mma_tf32(float d[4], const float a[4], const float b[2]) {
    unsigned const* A = reinterpret_cast<unsigned const*>(a);
    unsigned const* Bp = reinterpret_cast<unsigned const*>(b);
    asm volatile(
        "mma.sync.aligned.m16n8k8.row.col.f32.tf32.tf32.f32 "
        "{%0,%1,%2,%3}, {%4,%5,%6,%7}, {%8,%9}, {%0,%1,%2,%3};"
        : "+f"(d[0]), "+f"(d[1]), "+f"(d[2]), "+f"(d[3])
        : "r"(A[0]), "r"(A[1]), "r"(A[2]), "r"(A[3]),
          "r"(Bp[0]), "r"(Bp[1]));
}

// ---------------- cp.async helpers ----------------
__device__ __forceinline__ uint32_t smem_u32(const void* p) {
    uint32_t a;
    asm("{ .reg .u64 t; cvta.to.shared.u64 t, %1; cvt.u32.u64 %0, t; }"
        : "=r"(a) : "l"(p));
    return a;
}
#define CP_ASYNC16(dst, src) \
    asm volatile("cp.async.cg.shared.global [%0], [%1], 16;" \
                 :: "r"(dst), "l"(src) : "memory")
#define CP_COMMIT() asm volatile("cp.async.commit_group;" ::: "memory")
#define CP_WAIT0()  asm volatile("cp.async.wait_group 0;" ::: "memory")
#define CP_WAIT1()  asm volatile("cp.async.wait_group 1;" ::: "memory")

// =====================================================================
// Prep kernel: pack final_mat -> uchar; round+pad tables; round W's.
// grid: [0,2048) fm, 2048 tables, [2049, 2049+4096) the four W matrices
// =====================================================================
__global__ __launch_bounds__(256) void prep_kernel(
    const int* __restrict__ fm,
    const float* __restrict__ tk, const float* __restrict__ tv,
    const float* __restrict__ Wq, const float* __restrict__ Wk,
    const float* __restrict__ Wv, const float* __restrict__ Wo)
{
    const int bid = blockIdx.x;
    if (bid < 2048) {
        const int idx = bid * 1024 + threadIdx.x * 4;
        const int4 v = *reinterpret_cast<const int4*>(fm + idx);
        *reinterpret_cast<uchar4*>(g_fmb + idx) =
            make_uchar4((unsigned char)v.x, (unsigned char)v.y,
                        (unsigned char)v.z, (unsigned char)v.w);
    } else if (bid == 2048) {
        for (int i = threadIdx.x; i < 136 * 68; i += 256) {
            const int r = i / 68, c = i - r * 68;
            g_tk[i] = (r < TAB && c < 64) ? tf32r(tk[r * 64 + c]) : 0.f;
        }
        for (int i = threadIdx.x; i < 136 * 72; i += 256) {
            const int r = i / 72, c = i - r * 72;
            g_tv[i] = (r < TAB && c < 64) ? tf32r(tv[r * 64 + c]) : 0.f;
        }
    } else {
        const int r = bid - 2049;           // 0..4095
        const int w = r >> 10;              // matrix index
        const float* src = (w == 0) ? Wq : (w == 1) ? Wk : (w == 2) ? Wv : Wo;
        const int idx = (r & 1023) * 1024 + threadIdx.x * 4;
        float4 v = *reinterpret_cast<const float4*>(src + idx);
        *reinterpret_cast<float4*>(g_rW + (size_t)w * HID * HID + idx) = tf32r4(v);
    }
}

// =====================================================================
// GEMM v4: C[4096,1024] = A @ rW^T + bias. 128x256x16 tiles, 512 thr,
// 16 warps (4m x 4n), warp tile 32x64, double-buffered smem.
// B staged via cp.async (rW pre-rounded). A: either LDG+cvt+STS
// (A_PRE=false, raw inputs) or cp.async (A_PRE=true, pre-rounded g_X).
// =====================================================================
constexpr int BKS = 20;
constexpr int GA  = 128 * BKS;
constexpr int GB  = 256 * BKS;
constexpr size_t GEMM_SMEM = (size_t)2 * (GA + GB) * 4;  // 61,440 B

template <bool A_PRE, bool ROUND>
__device__ __forceinline__ void gemm_body(
    const float* __restrict__ A, const float* __restrict__ rW,
    const float* __restrict__ bias, float* __restrict__ C)
{
    extern __shared__ float dsm[];
    float* AsBase = dsm;
    float* BsBase = dsm + 2 * GA;

    const int tid  = threadIdx.x;
    const int m0   = blockIdx.y * 128;
    const int n0   = blockIdx.x * 256;
    const int lane = tid & 31;
    const int g    = lane >> 2;
    const int t    = lane & 3;
    const int warp = tid >> 5;
    const int wm   = warp >> 2;
    const int wn   = warp & 3;

    const int lr = tid >> 2;
    const int lc = (tid & 3) * 4;
    const float* Ap  = A  + (size_t)(m0 + lr) * HID + lc;
    const float* Bp0 = rW + (size_t)(n0 + lr) * HID + lc;
    const float* Bp1 = rW + (size_t)(n0 + lr + 128) * HID + lc;

    const uint32_t sb   = smem_u32(dsm);
    const uint32_t aOff = (uint32_t)(lr * BKS + lc) * 4;
    const uint32_t bOff0 = (uint32_t)(2 * GA + lr * BKS + lc) * 4;
    const uint32_t bOff1 = (uint32_t)(2 * GA + (lr + 128) * BKS + lc) * 4;

    float acc[2][8][4];
#pragma unroll
    for (int i = 0; i < 2; i++)
#pragma unroll
        for (int j = 0; j < 8; j++)
#pragma unroll
            for (int r = 0; r < 4; r++) acc[i][j][r] = 0.f;

    // ---- prologue: stage tile 0 into buffer 0 ----
    float4 pa;
    if (A_PRE) {
        CP_ASYNC16(sb + aOff, Ap);
    } else {
        pa = *reinterpret_cast<const float4*>(Ap);
        *reinterpret_cast<float4*>(AsBase + lr * BKS + lc) = tf32r4(pa);
    }
    CP_ASYNC16(sb + bOff0, Bp0);
    CP_ASYNC16(sb + bOff1, Bp1);
    CP_COMMIT();

    int buf = 0;
    for (int k0 = 0; k0 < HID; k0 += 16, buf ^= 1) {
        CP_WAIT0();
        __syncthreads();

        const bool more = (k0 + 16 < HID);
        if (more) {
            const uint32_t ba = (uint32_t)((buf ^ 1) * GB) * 4;
            if (A_PRE) {
                CP_ASYNC16(sb + aOff + (uint32_t)((buf ^ 1) * GA) * 4, Ap + k0 + 16);
            }
            CP_ASYNC16(sb + bOff0 + ba, Bp0 + k0 + 16);
            CP_ASYNC16(sb + bOff1 + ba, Bp1 + k0 + 16);
            CP_COMMIT();
            if (!A_PRE) pa = *reinterpret_cast<const float4*>(Ap + k0 + 16);
        }

        const float* As = AsBase + buf * GA;
        const float* Bs = BsBase + buf * GB;
#pragma unroll
        for (int ks = 0; ks < 2; ks++) {
            const int kc = ks * 8 + t;
            float afr[2][4], bfr[8][2];
#pragma unroll
            for (int mt = 0; mt < 2; mt++) {
                const int r = wm * 32 + mt * 16 + g;
                afr[mt][0] = As[(r    ) * BKS + kc];
                afr[mt][1] = As[(r + 8) * BKS + kc];
                afr[mt][2] = As[(r    ) * BKS + kc + 4];
                afr[mt][3] = As[(r + 8) * BKS + kc + 4];
            }
#pragma unroll
            for (int nt = 0; nt < 8; nt++) {
                const int n = wn * 64 + nt * 8 + g;
                bfr[nt][0] = Bs[n * BKS + kc];
                bfr[nt][1] = Bs[n * BKS + kc + 4];
            }
#pragma unroll
            for (int mt = 0; mt < 2; mt++)
#pragma unroll
                for (int nt = 0; nt < 8; nt++)
                    mma_tf32(acc[mt][nt], afr[mt], bfr[nt]);
        }

        if (more && !A_PRE) {
            *reinterpret_cast<float4*>(AsBase + (buf ^ 1) * GA + lr * BKS + lc) = tf32r4(pa);
        }
    }

#pragma unroll
    for (int mt = 0; mt < 2; mt++) {
        const int row0 = m0 + wm * 32 + mt * 16 + g;
#pragma unroll
        for (int nt = 0; nt < 8; nt++) {
            const int col = n0 + wn * 64 + nt * 8 + 2 * t;
            const float b0 = bias[col], b1 = bias[col + 1];
            float* c0 = C + (size_t)row0 * HID + col;
            float* c1 = C + (size_t)(row0 + 8) * HID + col;
            if (ROUND) {
                c0[0] = tf32r(acc[mt][nt][0] + b0); c0[1] = tf32r(acc[mt][nt][1] + b1);
                c1[0] = tf32r(acc[mt][nt][2] + b0); c1[1] = tf32r(acc[mt][nt][3] + b1);
            } else {
                c0[0] = acc[mt][nt][0] + b0; c0[1] = acc[mt][nt][1] + b1;
                c1[0] = acc[mt][nt][2] + b0; c1[1] = acc[mt][nt][3] + b1;
            }
        }
    }
}

__global__ __launch_bounds__(512, 1) void gemm_qkv(
    const float* __restrict__ q_in, const float* __restrict__ k_in,
    const float* __restrict__ v_in,
    const float* __restrict__ bq, const float* __restrict__ bk,
    const float* __restrict__ bv)
{
    if (blockIdx.z == 0)
        gemm_body<false, true>(q_in, g_rW + 0 * (size_t)HID * HID, bq, g_Q);
    else if (blockIdx.z == 1)
        gemm_body<false, true>(k_in, g_rW + 1 * (size_t)HID * HID, bk, g_K);
    else
        gemm_body<false, true>(v_in, g_rW + 2 * (size_t)HID * HID, bv, g_V);
}

__global__ __launch_bounds__(512, 1) void gemm_out(
    const float* __restrict__ bias, float* __restrict__ C)
{
    gemm_body<true, false>(g_X, g_rW + 3 * (size_t)HID * HID, bias, C);
}

// =====================================================================
// Fused MMA attention (R11, proven): cp.async staging, atomicAdd (RED)
// scatter, dual-accumulator w1/w2. block = (32 q, h, b), 512 threads.
// Only change vs R11: store g_X tf32-rounded (rounding moved here from
// gemm_out staging — value identical).
// =====================================================================
constexpr int OFF_P  = 2176;
constexpr int OFF_KV = 6400;
constexpr int OFF_S  = 24832;
constexpr int OFF_F  = 41344;
constexpr int SMF_TOTAL = OFF_F + (32 * 528) / 4;       // 45568 floats
constexpr size_t SMF_BYTES = (size_t)SMF_TOTAL * 4;     // 182,272 B

__global__ __launch_bounds__(512) void attn_fused_mma()
{
    extern __shared__ float smem[];
    float* sQ  = smem;                 // [32][68]
    float* sP  = smem + OFF_P;         // [32][132]
    float* sSb = smem;                 // [32][136] union
    float* sKV = smem + OFF_KV;
    float* sS  = smem + OFF_S;         // [32][516]
    unsigned char* sFb = reinterpret_cast<unsigned char*>(smem + OFF_F);

    const uint32_t sbase = smem_u32(smem);
    const uint32_t sQa  = sbase;
    const uint32_t sKVa = sbase + OFF_KV * 4;
    const uint32_t sFa  = sbase + OFF_F * 4;

    const int tid  = threadIdx.x;
    const int lane = tid & 31;
    const int warp = tid >> 5;
    const int g    = lane >> 2;
    const int t    = lane & 3;
    const int mh   = warp >> 3;        // 0..1
    const int wg   = warp & 7;         // 0..7
    const int mr   = mh * 16;
    const int q0   = blockIdx.x * 32;
    const int h    = blockIdx.y;
    const int b    = blockIdx.z;

    const float* gKb = g_K + (size_t)(b * L) * HID + h * HD;
    const float* gVb = g_V + (size_t)(b * L) * HID + h * HD;

    // ---------- stage 0: cp.async Q, table_k, fm ----------
    {
        const int q = tid >> 4, seg = tid & 15;
        CP_ASYNC16(sQa + (uint32_t)(q * 68 + seg * 4) * 4,
                   g_Q + (size_t)(b * L + q0 + q) * HID + h * HD + seg * 4);
    }
    for (int i = tid; i < (136 * 68) / 4; i += 512)
        CP_ASYNC16(sKVa + (uint32_t)i * 16, g_tk + i * 4);
    for (int i = tid; i < 32 * 32; i += 512) {
        const int q = i >> 5, seg = i & 31;
        CP_ASYNC16(sFa + (uint32_t)(q * 528 + seg * 16),
                   g_fmb + (size_t)(b * L + q0 + q) * L + seg * 16);
    }
    CP_COMMIT();
    CP_WAIT0();
    __syncthreads();

    // ---------- Q fragments into registers ----------
    float qf[8][4];
#pragma unroll
    for (int ks = 0; ks < 8; ks++) {
        const int kb = ks * 8;
        qf[ks][0] = sQ[(mr + g    ) * 68 + kb + t];
        qf[ks][1] = sQ[(mr + g + 8) * 68 + kb + t];
        qf[ks][2] = sQ[(mr + g    ) * 68 + kb + t + 4];
        qf[ks][3] = sQ[(mr + g + 8) * 68 + kb + t + 4];
    }

    // ---------- P[32][129] = Q @ table_k^T ----------
#pragma unroll
    for (int j = 0; j < 3; j++) {
        const int n8 = wg + 8 * j;
        if (n8 > 16) break;
        const int nb = n8 * 8;
        float acc[4] = {0.f, 0.f, 0.f, 0.f};
#pragma unroll
        for (int ks = 0; ks < 8; ks++) {
            const int kb = ks * 8;
            float bb[2];
            bb[0] = sKV[(nb + g) * 68 + kb + t];
            bb[1] = sKV[(nb + g) * 68 + kb + t + 4];
            mma_tf32(acc, qf[ks], bb);
        }
        const int c0 = nb + 2 * t;
        if (c0 < TAB) {
            sP[(mr + g    ) * 132 + c0] = acc[0];
            sP[(mr + g + 8) * 132 + c0] = acc[2];
        }
        if (c0 + 1 < TAB) {
            sP[(mr + g    ) * 132 + c0 + 1] = acc[1];
            sP[(mr + g + 8) * 132 + c0 + 1] = acc[3];
        }
    }
    __syncthreads();   // table_k reads complete

    // ---------- issue K tile 0 ----------
#pragma unroll
    for (int j = 0; j < 4; j++) {
        const int idx = tid + 512 * j, row = idx >> 4, seg = idx & 15;
        CP_ASYNC16(sKVa + (uint32_t)(row * 68 + seg * 4) * 4,
                   gKb + (size_t)row * HID + seg * 4);
    }
    CP_COMMIT();

    // ---------- scores: 4 K-tiles of 128, double-buffered ----------
#pragma unroll 1
    for (int kt = 0; kt < 4; kt++) {
        if (kt < 3) {
            const uint32_t dstb = sKVa + (uint32_t)(((kt + 1) & 1) * 8704) * 4;
#pragma unroll
            for (int j = 0; j < 4; j++) {
                const int idx = tid + 512 * j, row = idx >> 4, seg = idx & 15;
                CP_ASYNC16(dstb + (uint32_t)(row * 68 + seg * 4) * 4,
                           gKb + (size_t)((kt + 1) * 128 + row) * HID + seg * 4);
            }
            CP_COMMIT();
            CP_WAIT1();
        } else {
            CP_WAIT0();
        }
        __syncthreads();

        const float* Kb = sKV + (kt & 1) * 8704;
#pragma unroll
        for (int jj = 0; jj < 2; jj++) {
            const int nb = (wg * 2 + jj) * 8;
            float acc[4] = {0.f, 0.f, 0.f, 0.f};
#pragma unroll
            for (int ks = 0; ks < 8; ks++) {
                const int kb = ks * 8;
                float bb[2];
                bb[0] = Kb[(nb + g) * 68 + kb + t];
                bb[1] = Kb[(nb + g) * 68 + kb + t + 4];
                mma_tf32(acc, qf[ks], bb);
            }
            const int row0 = mr + g, row1 = row0 + 8;
            const int kc = kt * 128 + nb + 2 * t;
            const int t00 = sFb[row0 * 528 + kc], t01 = sFb[row0 * 528 + kc + 1];
            const int t10 = sFb[row1 * 528 + kc], t11 = sFb[row1 * 528 + kc + 1];
            sS[row0 * 516 + kc    ] = (acc[0] + sP[row0 * 132 + t00]) * 0.125f;
            sS[row0 * 516 + kc + 1] = (acc[1] + sP[row0 * 132 + t01]) * 0.125f;
            sS[row1 * 516 + kc    ] = (acc[2] + sP[row1 * 132 + t10]) * 0.125f;
            sS[row1 * 516 + kc + 1] = (acc[3] + sP[row1 * 132 + t11]) * 0.125f;
        }
        __syncthreads();
    }

    // ---------- issue V tile 0 (hides under softmax) ----------
#pragma unroll
    for (int j = 0; j < 4; j++) {
        const int idx = tid + 512 * j, row = idx >> 4, seg = idx & 15;
        CP_ASYNC16(sKVa + (uint32_t)(row * 72 + seg * 4) * 4,
                   gVb + (size_t)row * HID + seg * 4);
    }
    CP_COMMIT();

    // ---------- softmax (16 warps x 2 rows) ----------
    for (int r = warp * 2; r < warp * 2 + 2; r++) {
        float* row = sS + r * 516;
        float m = -1e30f;
#pragma unroll
        for (int i = 0; i < 16; i++) m = fmaxf(m, row[lane + 32 * i]);
#pragma unroll
        for (int o = 16; o > 0; o >>= 1) m = fmaxf(m, __shfl_xor_sync(0xffffffffu, m, o));
        float e[16];
        float s = 0.f;
#pragma unroll
        for (int i = 0; i < 16; i++) {
            e[i] = __expf(row[lane + 32 * i] - m);
            s += e[i];
        }
#pragma unroll
        for (int o = 16; o > 0; o >>= 1) s += __shfl_xor_sync(0xffffffffu, s, o);
        const float inv = 1.f / s;
#pragma unroll
        for (int i = 0; i < 16; i++) row[lane + 32 * i] = tf32r(e[i] * inv);
    }
    for (int i = tid; i < 32 * 136; i += 512) sSb[i] = 0.f;
    CP_WAIT0();
    __syncthreads();

    // ---------- w1 = attn @ V: 4 V-tiles of 128, double-buffered ----------
    const int nbw = wg * 8;
    float acc1a[4] = {0.f, 0.f, 0.f, 0.f};
    float acc1b[4] = {0.f, 0.f, 0.f, 0.f};
#pragma unroll 1
    for (int vt = 0; vt < 4; vt++) {
        if (vt < 3) {
            const uint32_t dstb = sKVa + (uint32_t)(((vt + 1) & 1) * 9216) * 4;
#pragma unroll
            for (int j = 0; j < 4; j++) {
                const int idx = tid + 512 * j, row = idx >> 4, seg = idx & 15;
                CP_ASYNC16(dstb + (uint32_t)(row * 72 + seg * 4) * 4,
                           gVb + (size_t)((vt + 1) * 128 + row) * HID + seg * 4);
            }
            CP_COMMIT();
            CP_WAIT1();
        } else {
            CP_WAIT0();
        }
        __syncthreads();

        const float* Vb = sKV + (vt & 1) * 9216;
        const int cb = vt * 128;
#pragma unroll
        for (int ks = 0; ks < 16; ks += 2) {
            {
                const int kb = ks * 8;
                float a[4], bb[2];
                a[0] = sS[(mr + g    ) * 516 + cb + kb + t];
                a[1] = sS[(mr + g + 8) * 516 + cb + kb + t];
                a[2] = sS[(mr + g    ) * 516 + cb + kb + t + 4];
                a[3] = sS[(mr + g + 8) * 516 + cb + kb + t + 4];
                bb[0] = Vb[(kb + t    ) * 72 + nbw + g];
                bb[1] = Vb[(kb + t + 4) * 72 + nbw + g];
                mma_tf32(acc1a, a, bb);
            }
            {
                const int kb = (ks + 1) * 8;
                float a[4], bb[2];
                a[0] = sS[(mr + g    ) * 516 + cb + kb + t];
                a[1] = sS[(mr + g + 8) * 516 + cb + kb + t];
                a[2] = sS[(mr + g    ) * 516 + cb + kb + t + 4];
                a[3] = sS[(mr + g + 8) * 516 + cb + kb + t + 4];
                bb[0] = Vb[(kb + t    ) * 72 + nbw + g];
                bb[1] = Vb[(kb + t + 4) * 72 + nbw + g];
                mma_tf32(acc1b, a, bb);
            }
        }
        __syncthreads();
    }

    // ---------- bucket scatter (RED, fire-and-forget) + stage table_v ----------
    {
        const int q  = tid >> 4;
        const int kg = tid & 15;
        const unsigned char* fr = sFb + q * 528;
        const float* ar = sS + q * 516;
        float* sbq = sSb + q * 136;
#pragma unroll 4
        for (int i = 0; i < 32; i++) {
            const int k = i * 16 + kg;
            atomicAdd(&sbq[fr[k]], ar[k]);
        }
    }
    for (int i = tid; i < (136 * 72) / 4; i += 512)
        CP_ASYNC16(sKVa + (uint32_t)i * 16, g_tv + i * 4);
    CP_COMMIT();
    CP_WAIT0();
    __syncthreads();

    // ---------- w2 = buckets @ table_v (17 k-steps, dual accumulators) ----------
    float acc2a[4] = {0.f, 0.f, 0.f, 0.f};
    float acc2b[4] = {0.f, 0.f, 0.f, 0.f};
#pragma unroll
    for (int ks = 0; ks < 17; ks++) {
        const int kb = ks * 8;
        float a[4], bb[2];
        a[0] = tf32r(sSb[(mr + g    ) * 136 + kb + t]);
        a[1] = tf32r(sSb[(mr + g + 8) * 136 + kb + t]);
        a[2] = tf32r(sSb[(mr + g    ) * 136 + kb + t + 4]);
        a[3] = tf32r(sSb[(mr + g + 8) * 136 + kb + t + 4]);
        bb[0] = sKV[(kb + t    ) * 72 + nbw + g];
        bb[1] = sKV[(kb + t + 4) * 72 + nbw + g];
        if (ks & 1) mma_tf32(acc2b, a, bb);
        else        mma_tf32(acc2a, a, bb);
    }

    // ---------- store (tf32-rounded: rounding moved from gemm_out staging) ----------
    {
        const int row0 = mr + g;
        const int col  = nbw + 2 * t;
        float2 o0 = make_float2(tf32r(acc1a[0] + acc1b[0] + acc2a[0] + acc2b[0]),
                                tf32r(acc1a[1] + acc1b[1] + acc2a[1] + acc2b[1]));
        float2 o1 = make_float2(tf32r(acc1a[2] + acc1b[2] + acc2a[2] + acc2b[2]),
                                tf32r(acc1a[3] + acc1b[3] + acc2a[3] + acc2b[3]));
        *reinterpret_cast<float2*>(
            g_X + (size_t)(b * L + q0 + row0) * HID + h * HD + col) = o0;
        *reinterpret_cast<float2*>(
            g_X + (size_t)(b * L + q0 + row0 + 8) * HID + h * HD + col) = o1;
    }
}

// =====================================================================
// launch
// =====================================================================
extern "C" void kernel_launch(void* const* d_in, const int* in_sizes, int n_in,
                              void* d_out, int out_size)
{
    const float* query   = (const float*)d_in[0];
    const float* key     = (const float*)d_in[1];
    const float* value   = (const float*)d_in[2];
    const int*   fm      = (const int*)  d_in[3];
    const float* Wq      = (const float*)d_in[4];
    const float* bq      = (const float*)d_in[5];
    const float* Wk      = (const float*)d_in[6];
    const float* bk      = (const float*)d_in[7];
    const float* Wv      = (const float*)d_in[8];
    const float* bv      = (const float*)d_in[9];
    const float* Wo      = (const float*)d_in[10];
    const float* bo      = (const float*)d_in[11];
    const float* table_k = (const float*)d_in[12];
    const float* table_v = (const float*)d_in[13];
    float* out = (float*)d_out;

    cudaFuncSetAttribute(attn_fused_mma,
                         cudaFuncAttributeMaxDynamicSharedMemorySize, (int)SMF_BYTES);
    cudaFuncSetAttribute(gemm_qkv,
                         cudaFuncAttributeMaxDynamicSharedMemorySize, (int)GEMM_SMEM);
    cudaFuncSetAttribute(gemm_out,
                         cudaFuncAttributeMaxDynamicSharedMemorySize, (int)GEMM_SMEM);

    prep_kernel<<<2049 + 4096, 256>>>(fm, table_k, table_v, Wq, Wk, Wv, Wo);

    const dim3 gqkv(HID / 256, BL / 128, 3);  // (4, 32, 3)
    gemm_qkv<<<gqkv, 512, GEMM_SMEM>>>(query, key, value, bq, bk, bv);

    const dim3 gattn(L / 32, H, B);  // (16, 16, 8)
    attn_fused_mma<<<gattn, 512, SMF_BYTES>>>();

    const dim3 gout(HID / 256, BL / 128);  // (4, 32)
    gemm_out<<<gout, 512, GEMM_SMEM>>>(bo, out);
}

// round 14
// speedup vs baseline: 1.0394x; 1.0289x over previous
#include <cuda_runtime.h>
#include <cstdint>

// ---------------- problem constants ----------------
constexpr int B    = 8;
constexpr int L    = 512;
constexpr int HID  = 1024;
constexpr int H    = 16;
constexpr int HD   = 64;     // head dim
constexpr int TAB  = 129;    // 2*64+1 relative-position table rows
constexpr int BL   = B * L;  // 4096

// ---------------- device scratch ----------------
__device__ float g_Q[BL * HID];
__device__ float g_K[BL * HID];
__device__ float g_V[BL * HID];
__device__ float g_X[BL * HID];                 // w1+w2 merged (tf32-rounded)
__device__ float g_rW[4 * HID * HID];           // pre-rounded Wq,Wk,Wv,Wo
__device__ unsigned char g_fmb[(size_t)B * L * L];  // final_mat as uchar (2 MB)
__device__ float g_tk[136 * 68];                // table_k tf32-rounded, padded
__device__ float g_tv[136 * 72];                // table_v tf32-rounded, padded

// =====================================================================
// tf32 helpers
// =====================================================================
__device__ __forceinline__ float tf32r(float x) {
    unsigned y;
    asm("cvt.rna.tf32.f32 %0, %1;" : "=r"(y) : "f"(x));
    return __uint_as_float(y);
}

__device__ __forceinline__ float4 tf32r4(float4 v) {
    return make_float4(tf32r(v.x), tf32r(v.y), tf32r(v.z), tf32r(v.w));
}

__device__ __forceinline__ void mma_tf32(float d[4], const float a[4], const float b[2]) {
    unsigned const* A = reinterpret_cast<unsigned const*>(a);
    unsigned const* Bp = reinterpret_cast<unsigned const*>(b);
    asm volatile(
        "mma.sync.aligned.m16n8k8.row.col.f32.tf32.tf32.f32 "
        "{%0,%1,%2,%3}, {%4,%5,%6,%7}, {%8,%9}, {%0,%1,%2,%3};"
        : "+f"(d[0]), "+f"(d[1]), "+f"(d[2]), "+f"(d[3])
        : "r"(A[0]), "r"(A[1]), "r"(A[2]), "r"(A[3]),
          "r"(Bp[0]), "r"(Bp[1]));
}

// ---------------- cp.async helpers ----------------
__device__ __forceinline__ uint32_t smem_u32(const void* p) {
    uint32_t a;
    asm("{ .reg .u64 t; cvta.to.shared.u64 t, %1; cvt.u32.u64 %0, t; }"
        : "=r"(a) : "l"(p));
    return a;
}
#define CP_ASYNC16(dst, src) \
    asm volatile("cp.async.cg.shared.global [%0], [%1], 16;" \
                 :: "r"(dst), "l"(src) : "memory")
#define CP_COMMIT() asm volatile("cp.async.commit_group;" ::: "memory")
#define CP_WAIT0()  asm volatile("cp.async.wait_group 0;" ::: "memory")
#define CP_WAIT1()  asm volatile("cp.async.wait_group 1;" ::: "memory")

// =====================================================================
// Prep kernel: pack final_mat -> uchar; round+pad tables; round W's.
// =====================================================================
__global__ __launch_bounds__(256) void prep_kernel(
    const int* __restrict__ fm,
    const float* __restrict__ tk, const float* __restrict__ tv,
    const float* __restrict__ Wq, const float* __restrict__ Wk,
    const float* __restrict__ Wv, const float* __restrict__ Wo)
{
    const int bid = blockIdx.x;
    if (bid < 2048) {
        const int idx = bid * 1024 + threadIdx.x * 4;
        const int4 v = *reinterpret_cast<const int4*>(fm + idx);
        *reinterpret_cast<uchar4*>(g_fmb + idx) =
            make_uchar4((unsigned char)v.x, (unsigned char)v.y,
                        (unsigned char)v.z, (unsigned char)v.w);
    } else if (bid == 2048) {
        for (int i = threadIdx.x; i < 136 * 68; i += 256) {
            const int r = i / 68, c = i - r * 68;
            g_tk[i] = (r < TAB && c < 64) ? tf32r(tk[r * 64 + c]) : 0.f;
        }
        for (int i = threadIdx.x; i < 136 * 72; i += 256) {
            const int r = i / 72, c = i - r * 72;
            g_tv[i] = (r < TAB && c < 64) ? tf32r(tv[r * 64 + c]) : 0.f;
        }
    } else {
        const int r = bid - 2049;           // 0..4095
        const int w = r >> 10;              // matrix index
        const float* src = (w == 0) ? Wq : (w == 1) ? Wk : (w == 2) ? Wv : Wo;
        const int idx = (r & 1023) * 1024 + threadIdx.x * 4;
        float4 v = *reinterpret_cast<const float4*>(src + idx);
        *reinterpret_cast<float4*>(g_rW + (size_t)w * HID * HID + idx) = tf32r4(v);
    }
}

// =====================================================================
// GEMM v5: 3-STAGE cp.async pipeline. C[4096,1024] = A @ rW^T + bias.
// 128x256x16 tiles, 512 thr, 16 warps (4m x 4n), warp tile 32x64.
// B (and A when A_PRE) triple-buffered; wait_group(1) gives every tile
// two compute phases of landing slack.
// =====================================================================
constexpr int BKS = 20;
constexpr int GA  = 128 * BKS;             // 2560 floats
constexpr int GB  = 256 * BKS;             // 5120 floats
constexpr size_t GEMM_SMEM = (size_t)3 * (GA + GB) * 4;  // 92,160 B
constexpr int NKT = HID / 16;              // 64 k-tiles

template <bool A_PRE, bool ROUND>
__device__ __forceinline__ void gemm_body(
    const float* __restrict__ A, const float* __restrict__ rW,
    const float* __restrict__ bias, float* __restrict__ C)
{
    extern __shared__ float dsm[];
    // layout: A buffers [3][GA] then B buffers [3][GB]
    const int tid  = threadIdx.x;
    const int m0   = blockIdx.y * 128;
    const int n0   = blockIdx.x * 256;
    const int lane = tid & 31;
    const int g    = lane >> 2;
    const int t    = lane & 3;
    const int warp = tid >> 5;
    const int wm   = warp >> 2;
    const int wn   = warp & 3;

    const int lr = tid >> 2;
    const int lc = (tid & 3) * 4;
    const float* Ap  = A  + (size_t)(m0 + lr) * HID + lc;
    const float* Bp0 = rW + (size_t)(n0 + lr) * HID + lc;
    const float* Bp1 = rW + (size_t)(n0 + lr + 128) * HID + lc;

    const uint32_t sb    = smem_u32(dsm);
    const uint32_t aOff  = (uint32_t)(lr * BKS + lc) * 4;
    const uint32_t bOff0 = (uint32_t)(3 * GA + lr * BKS + lc) * 4;
    const uint32_t bOff1 = (uint32_t)(3 * GA + (lr + 128) * BKS + lc) * 4;

    float acc[2][8][4];
#pragma unroll
    for (int i = 0; i < 2; i++)
#pragma unroll
        for (int j = 0; j < 8; j++)
#pragma unroll
            for (int r = 0; r < 4; r++) acc[i][j][r] = 0.f;

    // ---- prologue: tiles 0 and 1 ----
    float4 pa;
    if (A_PRE) {
        CP_ASYNC16(sb + aOff, Ap);
    } else {
        pa = *reinterpret_cast<const float4*>(Ap);
        *reinterpret_cast<float4*>(dsm + lr * BKS + lc) = tf32r4(pa);
    }
    CP_ASYNC16(sb + bOff0, Bp0);
    CP_ASYNC16(sb + bOff1, Bp1);
    CP_COMMIT();                           // group: tile 0

    if (A_PRE) CP_ASYNC16(sb + aOff + (uint32_t)GA * 4, Ap + 16);
    CP_ASYNC16(sb + bOff0 + (uint32_t)GB * 4, Bp0 + 16);
    CP_ASYNC16(sb + bOff1 + (uint32_t)GB * 4, Bp1 + 16);
    CP_COMMIT();                           // group: tile 1
    if (!A_PRE) pa = *reinterpret_cast<const float4*>(Ap + 16);   // tile 1 regs

    for (int kt = 0; kt < NKT; kt++) {
        CP_WAIT1();          // oldest pending (tile kt) landed; kt+1 may be in flight
        __syncthreads();

        const int kn = kt + 2;
        if (kn < NKT) {
            const int k0 = kn * 16;
            const uint32_t s3 = (uint32_t)(kn % 3);
            if (A_PRE) CP_ASYNC16(sb + aOff + s3 * GA * 4, Ap + k0);
            CP_ASYNC16(sb + bOff0 + s3 * GB * 4, Bp0 + k0);
            CP_ASYNC16(sb + bOff1 + s3 * GB * 4, Bp1 + k0);
        }
        CP_COMMIT();         // unconditional: keeps group counting exact at tail

        const float* As = dsm + (A_PRE ? (kt % 3) : (kt & 1)) * GA;
        const float* Bs = dsm + 3 * GA + (kt % 3) * GB;
#pragma unroll
        for (int ks = 0; ks < 2; ks++) {
            const int kc = ks * 8 + t;
            float afr[2][4], bfr[8][2];
#pragma unroll
            for (int mt = 0; mt < 2; mt++) {
                const int r = wm * 32 + mt * 16 + g;
                afr[mt][0] = As[(r    ) * BKS + kc];
                afr[mt][1] = As[(r + 8) * BKS + kc];
                afr[mt][2] = As[(r    ) * BKS + kc + 4];
                afr[mt][3] = As[(r + 8) * BKS + kc + 4];
            }
#pragma unroll
            for (int nt = 0; nt < 8; nt++) {
                const int n = wn * 64 + nt * 8 + g;
                bfr[nt][0] = Bs[n * BKS + kc];
                bfr[nt][1] = Bs[n * BKS + kc + 4];
            }
#pragma unroll
            for (int mt = 0; mt < 2; mt++)
#pragma unroll
                for (int nt = 0; nt < 8; nt++)
                    mma_tf32(acc[mt][nt], afr[mt], bfr[nt]);
        }

        if (!A_PRE && kt + 1 < NKT) {
            // stage A tile kt+1 (regs -> smem), prefetch tile kt+2 regs
            *reinterpret_cast<float4*>(dsm + ((kt + 1) & 1) * GA + lr * BKS + lc) = tf32r4(pa);
            if (kt + 2 < NKT)
                pa = *reinterpret_cast<const float4*>(Ap + (kt + 2) * 16);
        }
    }

#pragma unroll
    for (int mt = 0; mt < 2; mt++) {
        const int row0 = m0 + wm * 32 + mt * 16 + g;
#pragma unroll
        for (int nt = 0; nt < 8; nt++) {
            const int col = n0 + wn * 64 + nt * 8 + 2 * t;
            const float b0 = bias[col], b1 = bias[col + 1];
            float* c0 = C + (size_t)row0 * HID + col;
            float* c1 = C + (size_t)(row0 + 8) * HID + col;
            if (ROUND) {
                c0[0] = tf32r(acc[mt][nt][0] + b0); c0[1] = tf32r(acc[mt][nt][1] + b1);
                c1[0] = tf32r(acc[mt][nt][2] + b0); c1[1] = tf32r(acc[mt][nt][3] + b1);
            } else {
                c0[0] = acc[mt][nt][0] + b0; c0[1] = acc[mt][nt][1] + b1;
                c1[0] = acc[mt][nt][2] + b0; c1[1] = acc[mt][nt][3] + b1;
            }
        }
    }
}

__global__ __launch_bounds__(512, 1) void gemm_qkv(
    const float* __restrict__ q_in, const float* __restrict__ k_in,
    const float* __restrict__ v_in,
    const float* __restrict__ bq, const float* __restrict__ bk,
    const float* __restrict__ bv)
{
    if (blockIdx.z == 0)
        gemm_body<false, true>(q_in, g_rW + 0 * (size_t)HID * HID, bq, g_Q);
    else if (blockIdx.z == 1)
        gemm_body<false, true>(k_in, g_rW + 1 * (size_t)HID * HID, bk, g_K);
    else
        gemm_body<false, true>(v_in, g_rW + 2 * (size_t)HID * HID, bv, g_V);
}

__global__ __launch_bounds__(512, 1) void gemm_out(
    const float* __restrict__ bias, float* __restrict__ C)
{
    gemm_body<true, false>(g_X, g_rW + 3 * (size_t)HID * HID, bias, C);
}

// =====================================================================
// Fused MMA attention (R11/R13, proven): cp.async staging, RED scatter,
// dual-accumulator w1/w2. block = (32 q, h, b), 512 threads.
// =====================================================================
constexpr int OFF_P  = 2176;
constexpr int OFF_KV = 6400;
constexpr int OFF_S  = 24832;
constexpr int OFF_F  = 41344;
constexpr int SMF_TOTAL = OFF_F + (32 * 528) / 4;       // 45568 floats
constexpr size_t SMF_BYTES = (size_t)SMF_TOTAL * 4;     // 182,272 B

__global__ __launch_bounds__(512) void attn_fused_mma()
{
    extern __shared__ float smem[];
    float* sQ  = smem;                 // [32][68]
    float* sP  = smem + OFF_P;         // [32][132]
    float* sSb = smem;                 // [32][136] union
    float* sKV = smem + OFF_KV;
    float* sS  = smem + OFF_S;         // [32][516]
    unsigned char* sFb = reinterpret_cast<unsigned char*>(smem + OFF_F);

    const uint32_t sbase = smem_u32(smem);
    const uint32_t sQa  = sbase;
    const uint32_t sKVa = sbase + OFF_KV * 4;
    const uint32_t sFa  = sbase + OFF_F * 4;

    const int tid  = threadIdx.x;
    const int lane = tid & 31;
    const int warp = tid >> 5;
    const int g    = lane >> 2;
    const int t    = lane & 3;
    const int mh   = warp >> 3;        // 0..1
    const int wg   = warp & 7;         // 0..7
    const int mr   = mh * 16;
    const int q0   = blockIdx.x * 32;
    const int h    = blockIdx.y;
    const int b    = blockIdx.z;

    const float* gKb = g_K + (size_t)(b * L) * HID + h * HD;
    const float* gVb = g_V + (size_t)(b * L) * HID + h * HD;

    // ---------- stage 0: cp.async Q, table_k, fm ----------
    {
        const int q = tid >> 4, seg = tid & 15;
        CP_ASYNC16(sQa + (uint32_t)(q * 68 + seg * 4) * 4,
                   g_Q + (size_t)(b * L + q0 + q) * HID + h * HD + seg * 4);
    }
    for (int i = tid; i < (136 * 68) / 4; i += 512)
        CP_ASYNC16(sKVa + (uint32_t)i * 16, g_tk + i * 4);
    for (int i = tid; i < 32 * 32; i += 512) {
        const int q = i >> 5, seg = i & 31;
        CP_ASYNC16(sFa + (uint32_t)(q * 528 + seg * 16),
                   g_fmb + (size_t)(b * L + q0 + q) * L + seg * 16);
    }
    CP_COMMIT();
    CP_WAIT0();
    __syncthreads();

    // ---------- Q fragments into registers ----------
    float qf[8][4];
#pragma unroll
    for (int ks = 0; ks < 8; ks++) {
        const int kb = ks * 8;
        qf[ks][0] = sQ[(mr + g    ) * 68 + kb + t];
        qf[ks][1] = sQ[(mr + g + 8) * 68 + kb + t];
        qf[ks][2] = sQ[(mr + g    ) * 68 + kb + t + 4];
        qf[ks][3] = sQ[(mr + g + 8) * 68 + kb + t + 4];
    }

    // ---------- P[32][129] = Q @ table_k^T ----------
#pragma unroll
    for (int j = 0; j < 3; j++) {
        const int n8 = wg + 8 * j;
        if (n8 > 16) break;
        const int nb = n8 * 8;
        float acc[4] = {0.f, 0.f, 0.f, 0.f};
#pragma unroll
        for (int ks = 0; ks < 8; ks++) {
            const int kb = ks * 8;
            float bb[2];
            bb[0] = sKV[(nb + g) * 68 + kb + t];
            bb[1] = sKV[(nb + g) * 68 + kb + t + 4];
            mma_tf32(acc, qf[ks], bb);
        }
        const int c0 = nb + 2 * t;
        if (c0 < TAB) {
            sP[(mr + g    ) * 132 + c0] = acc[0];
            sP[(mr + g + 8) * 132 + c0] = acc[2];
        }
        if (c0 + 1 < TAB) {
            sP[(mr + g    ) * 132 + c0 + 1] = acc[1];
            sP[(mr + g + 8) * 132 + c0 + 1] = acc[3];
        }
    }
    __syncthreads();   // table_k reads complete

    // ---------- issue K tile 0 ----------
#pragma unroll
    for (int j = 0; j < 4; j++) {
        const int idx = tid + 512 * j, row = idx >> 4, seg = idx & 15;
        CP_ASYNC16(sKVa + (uint32_t)(row * 68 + seg * 4) * 4,
                   gKb + (size_t)row * HID + seg * 4);
    }
    CP_COMMIT();

    // ---------- scores: 4 K-tiles of 128, double-buffered ----------
#pragma unroll 1
    for (int kt = 0; kt < 4; kt++) {
        if (kt < 3) {
            const uint32_t dstb = sKVa + (uint32_t)(((kt + 1) & 1) * 8704) * 4;
#pragma unroll
            for (int j = 0; j < 4; j++) {
                const int idx = tid + 512 * j, row = idx >> 4, seg = idx & 15;
                CP_ASYNC16(dstb + (uint32_t)(row * 68 + seg * 4) * 4,
                           gKb + (size_t)((kt + 1) * 128 + row) * HID + seg * 4);
            }
            CP_COMMIT();
            CP_WAIT1();
        } else {
            CP_WAIT0();
        }
        __syncthreads();

        const float* Kb = sKV + (kt & 1) * 8704;
#pragma unroll
        for (int jj = 0; jj < 2; jj++) {
            const int nb = (wg * 2 + jj) * 8;
            float acc[4] = {0.f, 0.f, 0.f, 0.f};
#pragma unroll
            for (int ks = 0; ks < 8; ks++) {
                const int kb = ks * 8;
                float bb[2];
                bb[0] = Kb[(nb + g) * 68 + kb + t];
                bb[1] = Kb[(nb + g) * 68 + kb + t + 4];
                mma_tf32(acc, qf[ks], bb);
            }
            const int row0 = mr + g, row1 = row0 + 8;
            const int kc = kt * 128 + nb + 2 * t;
            const int t00 = sFb[row0 * 528 + kc], t01 = sFb[row0 * 528 + kc + 1];
            const int t10 = sFb[row1 * 528 + kc], t11 = sFb[row1 * 528 + kc + 1];
            sS[row0 * 516 + kc    ] = (acc[0] + sP[row0 * 132 + t00]) * 0.125f;
            sS[row0 * 516 + kc + 1] = (acc[1] + sP[row0 * 132 + t01]) * 0.125f;
            sS[row1 * 516 + kc    ] = (acc[2] + sP[row1 * 132 + t10]) * 0.125f;
            sS[row1 * 516 + kc + 1] = (acc[3] + sP[row1 * 132 + t11]) * 0.125f;
        }
        __syncthreads();
    }

    // ---------- issue V tile 0 (hides under softmax) ----------
#pragma unroll
    for (int j = 0; j < 4; j++) {
        const int idx = tid + 512 * j, row = idx >> 4, seg = idx & 15;
        CP_ASYNC16(sKVa + (uint32_t)(row * 72 + seg * 4) * 4,
                   gVb + (size_t)row * HID + seg * 4);
    }
    CP_COMMIT();

    // ---------- softmax (16 warps x 2 rows) ----------
    for (int r = warp * 2; r < warp * 2 + 2; r++) {
        float* row = sS + r * 516;
        float m = -1e30f;
#pragma unroll
        for (int i = 0; i < 16; i++) m = fmaxf(m, row[lane + 32 * i]);
#pragma unroll
        for (int o = 16; o > 0; o >>= 1) m = fmaxf(m, __shfl_xor_sync(0xffffffffu, m, o));
        float e[16];
        float s = 0.f;
#pragma unroll
        for (int i = 0; i < 16; i++) {
            e[i] = __expf(row[lane + 32 * i] - m);
            s += e[i];
        }
#pragma unroll
        for (int o = 16; o > 0; o >>= 1) s += __shfl_xor_sync(0xffffffffu, s, o);
        const float inv = 1.f / s;
#pragma unroll
        for (int i = 0; i < 16; i++) row[lane + 32 * i] = tf32r(e[i] * inv);
    }
    for (int i = tid; i < 32 * 136; i += 512) sSb[i] = 0.f;
    CP_WAIT0();
    __syncthreads();

    // ---------- w1 = attn @ V: 4 V-tiles of 128, double-buffered ----------
    const int nbw = wg * 8;
    float acc1a[4] = {0.f, 0.f, 0.f, 0.f};
    float acc1b[4] = {0.f, 0.f, 0.f, 0.f};
#pragma unroll 1
    for (int vt = 0; vt < 4; vt++) {
        if (vt < 3) {
            const uint32_t dstb = sKVa + (uint32_t)(((vt + 1) & 1) * 9216) * 4;
#pragma unroll
            for (int j = 0; j < 4; j++) {
                const int idx = tid + 512 * j, row = idx >> 4, seg = idx & 15;
                CP_ASYNC16(dstb + (uint32_t)(row * 72 + seg * 4) * 4,
                           gVb + (size_t)((vt + 1) * 128 + row) * HID + seg * 4);
            }
            CP_COMMIT();
            CP_WAIT1();
        } else {
            CP_WAIT0();
        }
        __syncthreads();

        const float* Vb = sKV + (vt & 1) * 9216;
        const int cb = vt * 128;
#pragma unroll
        for (int ks = 0; ks < 16; ks += 2) {
            {
                const int kb = ks * 8;
                float a[4], bb[2];
                a[0] = sS[(mr + g    ) * 516 + cb + kb + t];
                a[1] = sS[(mr + g + 8) * 516 + cb + kb + t];
                a[2] = sS[(mr + g    ) * 516 + cb + kb + t + 4];
                a[3] = sS[(mr + g + 8) * 516 + cb + kb + t + 4];
                bb[0] = Vb[(kb + t    ) * 72 + nbw + g];
                bb[1] = Vb[(kb + t + 4) * 72 + nbw + g];
                mma_tf32(acc1a, a, bb);
            }
            {
                const int kb = (ks + 1) * 8;
                float a[4], bb[2];
                a[0] = sS[(mr + g    ) * 516 + cb + kb + t];
                a[1] = sS[(mr + g + 8) * 516 + cb + kb + t];
                a[2] = sS[(mr + g    ) * 516 + cb + kb + t + 4];
                a[3] = sS[(mr + g + 8) * 516 + cb + kb + t + 4];
                bb[0] = Vb[(kb + t    ) * 72 + nbw + g];
                bb[1] = Vb[(kb + t + 4) * 72 + nbw + g];
                mma_tf32(acc1b, a, bb);
            }
        }
        __syncthreads();
    }

    // ---------- bucket scatter (RED) + stage table_v ----------
    {
        const int q  = tid >> 4;
        const int kg = tid & 15;
        const unsigned char* fr = sFb + q * 528;
        const float* ar = sS + q * 516;
        float* sbq = sSb + q * 136;
#pragma unroll 4
        for (int i = 0; i < 32; i++) {
            const int k = i * 16 + kg;
            atomicAdd(&sbq[fr[k]], ar[k]);
        }
    }
    for (int i = tid; i < (136 * 72) / 4; i += 512)
        CP_ASYNC16(sKVa + (uint32_t)i * 16, g_tv + i * 4);
    CP_COMMIT();
    CP_WAIT0();
    __syncthreads();

    // ---------- w2 = buckets @ table_v (17 k-steps, dual accumulators) ----------
    float acc2a[4] = {0.f, 0.f, 0.f, 0.f};
    float acc2b[4] = {0.f, 0.f, 0.f, 0.f};
#pragma unroll
    for (int ks = 0; ks < 17; ks++) {
        const int kb = ks * 8;
        float a[4], bb[2];
        a[0] = tf32r(sSb[(mr + g    ) * 136 + kb + t]);
        a[1] = tf32r(sSb[(mr + g + 8) * 136 + kb + t]);
        a[2] = tf32r(sSb[(mr + g    ) * 136 + kb + t + 4]);
        a[3] = tf32r(sSb[(mr + g + 8) * 136 + kb + t + 4]);
        bb[0] = sKV[(kb + t    ) * 72 + nbw + g];
        bb[1] = sKV[(kb + t + 4) * 72 + nbw + g];
        if (ks & 1) mma_tf32(acc2b, a, bb);
        else        mma_tf32(acc2a, a, bb);
    }

    // ---------- store (tf32-rounded for gemm_out's cp.async A path) ----------
    {
        const int row0 = mr + g;
        const int col  = nbw + 2 * t;
        float2 o0 = make_float2(tf32r(acc1a[0] + acc1b[0] + acc2a[0] + acc2b[0]),
                                tf32r(acc1a[1] + acc1b[1] + acc2a[1] + acc2b[1]));
        float2 o1 = make_float2(tf32r(acc1a[2] + acc1b[2] + acc2a[2] + acc2b[2]),
                                tf32r(acc1a[3] + acc1b[3] + acc2a[3] + acc2b[3]));
        *reinterpret_cast<float2*>(
            g_X + (size_t)(b * L + q0 + row0) * HID + h * HD + col) = o0;
        *reinterpret_cast<float2*>(
            g_X + (size_t)(b * L + q0 + row0 + 8) * HID + h * HD + col) = o1;
    }
}

// =====================================================================
// launch
// =====================================================================
extern "C" void kernel_launch(void* const* d_in, const int* in_sizes, int n_in,
                              void* d_out, int out_size)
{
    const float* query   = (const float*)d_in[0];
    const float* key     = (const float*)d_in[1];
    const float* value   = (const float*)d_in[2];
    const int*   fm      = (const int*)  d_in[3];
    const float* Wq      = (const float*)d_in[4];
    const float* bq      = (const float*)d_in[5];
    const float* Wk      = (const float*)d_in[6];
    const float* bk      = (const float*)d_in[7];
    const float* Wv      = (const float*)d_in[8];
    const float* bv      = (const float*)d_in[9];
    const float* Wo      = (const float*)d_in[10];
    const float* bo      = (const float*)d_in[11];
    const float* table_k = (const float*)d_in[12];
    const float* table_v = (const float*)d_in[13];
    float* out = (float*)d_out;

    cudaFuncSetAttribute(attn_fused_mma,
                         cudaFuncAttributeMaxDynamicSharedMemorySize, (int)SMF_BYTES);
    cudaFuncSetAttribute(gemm_qkv,
                         cudaFuncAttributeMaxDynamicSharedMemorySize, (int)GEMM_SMEM);
    cudaFuncSetAttribute(gemm_out,
                         cudaFuncAttributeMaxDynamicSharedMemorySize, (int)GEMM_SMEM);

    prep_kernel<<<2049 + 4096, 256>>>(fm, table_k, table_v, Wq, Wk, Wv, Wo);

    const dim3 gqkv(HID / 256, BL / 128, 3);  // (4, 32, 3)
    gemm_qkv<<<gqkv, 512, GEMM_SMEM>>>(query, key, value, bq, bk, bv);

    const dim3 gattn(L / 32, H, B);  // (16, 16, 8)
    attn_fused_mma<<<gattn, 512, SMF_BYTES>>>();

    const dim3 gout(HID / 256, BL / 128);  // (4, 32)
    gemm_out<<<gout, 512, GEMM_SMEM>>>(bo, out);
}

// round 15
// speedup vs baseline: 1.0924x; 1.0510x over previous
#include <cuda_runtime.h>
#include <cstdint>

// ---------------- problem constants ----------------
constexpr int B    = 8;
constexpr int L    = 512;
constexpr int HID  = 1024;
constexpr int H    = 16;
constexpr int HD   = 64;     // head dim
constexpr int TAB  = 129;    // 2*64+1 relative-position table rows
constexpr int BL   = B * L;  // 4096

// ---------------- device scratch ----------------
__device__ float g_Q[BL * HID];
__device__ float g_K[BL * HID];
__device__ float g_V[BL * HID];
__device__ float g_X[BL * HID];                 // w1+w2 merged (tf32-rounded)
__device__ float g_rW[4 * HID * HID];           // pre-rounded Wq,Wk,Wv,Wo
__device__ unsigned char g_fmb[(size_t)B * L * L];  // final_mat as uchar (2 MB)
__device__ float g_tk[136 * 68];                // table_k tf32-rounded, padded
__device__ float g_tv[136 * 72];                // table_v tf32-rounded, padded

// =====================================================================
// tf32 helpers
// =====================================================================
__device__ __forceinline__ float tf32r(float x) {
    unsigned y;
    asm("cvt.rna.tf32.f32 %0, %1;" : "=r"(y) : "f"(x));
    return __uint_as_float(y);
}

__device__ __forceinline__ float4 tf32r4(float4 v) {
    return make_float4(tf32r(v.x), tf32r(v.y), tf32r(v.z), tf32r(v.w));
}

__device__ __forceinline__ void mma_tf32(float d[4], const float a[4], const float b[2]) {
    unsigned const* A = reinterpret_cast<unsigned const*>(a);
    unsigned const* Bp = reinterpret_cast<unsigned const*>(b);
    asm volatile(
        "mma.sync.aligned.m16n8k8.row.col.f32.tf32.tf32.f32 "
        "{%0,%1,%2,%3}, {%4,%5,%6,%7}, {%8,%9}, {%0,%1,%2,%3};"
        : "+f"(d[0]), "+f"(d[1]), "+f"(d[2]), "+f"(d[3])
        : "r"(A[0]), "r"(A[1]), "r"(A[2]), "r"(A[3]),
          "r"(Bp[0]), "r"(Bp[1]));
}

// ---------------- cp.async helpers ----------------
__device__ __forceinline__ uint32_t smem_u32(const void* p) {
    uint32_t a;
    asm("{ .reg .u64 t; cvta.to.shared.u64 t, %1; cvt.u32.u64 %0, t; }"
        : "=r"(a) : "l"(p));
    return a;
}
#define CP_ASYNC16(dst, src) \
    asm volatile("cp.async.cg.shared.global [%0], [%1], 16;" \
                 :: "r"(dst), "l"(src) : "memory")
#define CP_COMMIT() asm volatile("cp.async.commit_group;" ::: "memory")
#define CP_WAIT0()  asm volatile("cp.async.wait_group 0;" ::: "memory")
#define CP_WAIT1()  asm volatile("cp.async.wait_group 1;" ::: "memory")

// =====================================================================
// Prep kernel: pack final_mat -> uchar; round+pad tables; round W's.
// =====================================================================
__global__ __launch_bounds__(256) void prep_kernel(
    const int* __restrict__ fm,
    const float* __restrict__ tk, const float* __restrict__ tv,
    const float* __restrict__ Wq, const float* __restrict__ Wk,
    const float* __restrict__ Wv, const float* __restrict__ Wo)
{
    const int bid = blockIdx.x;
    if (bid < 2048) {
        const int idx = bid * 1024 + threadIdx.x * 4;
        const int4 v = *reinterpret_cast<const int4*>(fm + idx);
        *reinterpret_cast<uchar4*>(g_fmb + idx) =
            make_uchar4((unsigned char)v.x, (unsigned char)v.y,
                        (unsigned char)v.z, (unsigned char)v.w);
    } else if (bid == 2048) {
        for (int i = threadIdx.x; i < 136 * 68; i += 256) {
            const int r = i / 68, c = i - r * 68;
            g_tk[i] = (r < TAB && c < 64) ? tf32r(tk[r * 64 + c]) : 0.f;
        }
        for (int i = threadIdx.x; i < 136 * 72; i += 256) {
            const int r = i / 72, c = i - r * 72;
            g_tv[i] = (r < TAB && c < 64) ? tf32r(tv[r * 64 + c]) : 0.f;
        }
    } else {
        const int r = bid - 2049;           // 0..4095
        const int w = r >> 10;              // matrix index
        const float* src = (w == 0) ? Wq : (w == 1) ? Wk : (w == 2) ? Wv : Wo;
        const int idx = (r & 1023) * 1024 + threadIdx.x * 4;
        float4 v = *reinterpret_cast<const float4*>(src + idx);
        *reinterpret_cast<float4*>(g_rW + (size_t)w * HID * HID + idx) = tf32r4(v);
    }
}

// =====================================================================
// GEMM v6: BK=32, 3-stage cp.async pipeline. C[4096,1024] = A @ rW^T + bias.
// 128x256x32 tiles, 512 thr, 16 warps (4m x 4n), warp tile 32x64.
// 32 k-iterations (half the barriers of v5); 166 KB smem, 1 block/SM.
// =====================================================================
constexpr int BKS = 36;                    // 32 + 4 pad (proven conflict-free)
constexpr int GA  = 128 * BKS;             // 4608 floats
constexpr int GB  = 256 * BKS;             // 9216 floats
constexpr size_t GEMM_SMEM = (size_t)3 * (GA + GB) * 4;  // 165,888 B
constexpr int NKT = HID / 32;              // 32 k-tiles

template <bool A_PRE, bool ROUND>
__device__ __forceinline__ void gemm_body(
    const float* __restrict__ A, const float* __restrict__ rW,
    const float* __restrict__ bias, float* __restrict__ C)
{
    extern __shared__ float dsm[];
    // layout: A buffers [3][GA] then B buffers [3][GB]
    const int tid  = threadIdx.x;
    const int m0   = blockIdx.y * 128;
    const int n0   = blockIdx.x * 256;
    const int lane = tid & 31;
    const int g    = lane >> 2;
    const int t    = lane & 3;
    const int warp = tid >> 5;
    const int wm   = warp >> 2;
    const int wn   = warp & 3;

    // staging mapping: 8 threads per row, one float4 each (32 floats/row)
    const int lrow = tid >> 3;          // 0..63
    const int lseg = (tid & 7) * 4;     // 0..28
    const float* ApS = A  + (size_t)(m0 + lrow) * HID + lseg;          // +64-row step
    const float* BpS = rW + (size_t)(n0 + lrow) * HID + lseg;          // +64-row steps

    const uint32_t sb = smem_u32(dsm);
    // smem staging offsets (bytes)
    const uint32_t aO = (uint32_t)(lrow * BKS + lseg) * 4;
    const uint32_t bO = (uint32_t)(3 * GA + lrow * BKS + lseg) * 4;

    float acc[2][8][4];
#pragma unroll
    for (int i = 0; i < 2; i++)
#pragma unroll
        for (int j = 0; j < 8; j++)
#pragma unroll
            for (int r = 0; r < 4; r++) acc[i][j][r] = 0.f;

    // ---- prologue: tiles 0 and 1 ----
    float4 pa[2];
    if (A_PRE) {
#pragma unroll
        for (int j = 0; j < 2; j++)
            CP_ASYNC16(sb + aO + (uint32_t)(64 * j * BKS) * 4,
                       ApS + (size_t)(64 * j) * HID);
    } else {
#pragma unroll
        for (int j = 0; j < 2; j++) {
            pa[j] = *reinterpret_cast<const float4*>(ApS + (size_t)(64 * j) * HID);
            *reinterpret_cast<float4*>(dsm + (lrow + 64 * j) * BKS + lseg) = tf32r4(pa[j]);
        }
    }
#pragma unroll
    for (int j = 0; j < 4; j++)
        CP_ASYNC16(sb + bO + (uint32_t)(64 * j * BKS) * 4,
                   BpS + (size_t)(64 * j) * HID);
    CP_COMMIT();                           // group: tile 0

    if (A_PRE) {
#pragma unroll
        for (int j = 0; j < 2; j++)
            CP_ASYNC16(sb + aO + (uint32_t)(GA + 64 * j * BKS) * 4,
                       ApS + (size_t)(64 * j) * HID + 32);
    }
#pragma unroll
    for (int j = 0; j < 4; j++)
        CP_ASYNC16(sb + bO + (uint32_t)(GB + 64 * j * BKS) * 4,
                   BpS + (size_t)(64 * j) * HID + 32);
    CP_COMMIT();                           // group: tile 1
    if (!A_PRE) {
#pragma unroll
        for (int j = 0; j < 2; j++)
            pa[j] = *reinterpret_cast<const float4*>(ApS + (size_t)(64 * j) * HID + 32);
    }

    for (int kt = 0; kt < NKT; kt++) {
        CP_WAIT1();          // oldest pending (tile kt) landed
        __syncthreads();

        const int kn = kt + 2;
        if (kn < NKT) {
            const int k0 = kn * 32;
            const uint32_t s3 = (uint32_t)(kn % 3);
            if (A_PRE) {
#pragma unroll
                for (int j = 0; j < 2; j++)
                    CP_ASYNC16(sb + aO + (s3 * GA + (uint32_t)(64 * j * BKS)) * 4,
                               ApS + (size_t)(64 * j) * HID + k0);
            }
#pragma unroll
            for (int j = 0; j < 4; j++)
                CP_ASYNC16(sb + bO + (s3 * GB + (uint32_t)(64 * j * BKS)) * 4,
                           BpS + (size_t)(64 * j) * HID + k0);
        }
        CP_COMMIT();         // unconditional: exact group counting at tail

        const float* As = dsm + (kt % 3) * GA;
        const float* Bs = dsm + 3 * GA + (kt % 3) * GB;
#pragma unroll
        for (int ks = 0; ks < 4; ks++) {
            const int kc = ks * 8 + t;
            float afr[2][4], bfr[8][2];
#pragma unroll
            for (int mt = 0; mt < 2; mt++) {
                const int r = wm * 32 + mt * 16 + g;
                afr[mt][0] = As[(r    ) * BKS + kc];
                afr[mt][1] = As[(r + 8) * BKS + kc];
                afr[mt][2] = As[(r    ) * BKS + kc + 4];
                afr[mt][3] = As[(r + 8) * BKS + kc + 4];
            }
#pragma unroll
            for (int nt = 0; nt < 8; nt++) {
                const int n = wn * 64 + nt * 8 + g;
                bfr[nt][0] = Bs[n * BKS + kc];
                bfr[nt][1] = Bs[n * BKS + kc + 4];
            }
#pragma unroll
            for (int mt = 0; mt < 2; mt++)
#pragma unroll
                for (int nt = 0; nt < 8; nt++)
                    mma_tf32(acc[mt][nt], afr[mt], bfr[nt]);
        }

        if (!A_PRE && kt + 1 < NKT) {
            // stage A tile kt+1 (regs -> smem slot (kt+1)%3), prefetch tile kt+2
            float* ad = dsm + ((kt + 1) % 3) * GA;
#pragma unroll
            for (int j = 0; j < 2; j++)
                *reinterpret_cast<float4*>(ad + (lrow + 64 * j) * BKS + lseg) = tf32r4(pa[j]);
            if (kt + 2 < NKT) {
#pragma unroll
                for (int j = 0; j < 2; j++)
                    pa[j] = *reinterpret_cast<const float4*>(
                        ApS + (size_t)(64 * j) * HID + (kt + 2) * 32);
            }
        }
    }

#pragma unroll
    for (int mt = 0; mt < 2; mt++) {
        const int row0 = m0 + wm * 32 + mt * 16 + g;
#pragma unroll
        for (int nt = 0; nt < 8; nt++) {
            const int col = n0 + wn * 64 + nt * 8 + 2 * t;
            const float b0 = bias[col], b1 = bias[col + 1];
            float* c0 = C + (size_t)row0 * HID + col;
            float* c1 = C + (size_t)(row0 + 8) * HID + col;
            if (ROUND) {
                c0[0] = tf32r(acc[mt][nt][0] + b0); c0[1] = tf32r(acc[mt][nt][1] + b1);
                c1[0] = tf32r(acc[mt][nt][2] + b0); c1[1] = tf32r(acc[mt][nt][3] + b1);
            } else {
                c0[0] = acc[mt][nt][0] + b0; c0[1] = acc[mt][nt][1] + b1;
                c1[0] = acc[mt][nt][2] + b0; c1[1] = acc[mt][nt][3] + b1;
            }
        }
    }
}

__global__ __launch_bounds__(512, 1) void gemm_qkv(
    const float* __restrict__ q_in, const float* __restrict__ k_in,
    const float* __restrict__ v_in,
    const float* __restrict__ bq, const float* __restrict__ bk,
    const float* __restrict__ bv)
{
    if (blockIdx.z == 0)
        gemm_body<false, true>(q_in, g_rW + 0 * (size_t)HID * HID, bq, g_Q);
    else if (blockIdx.z == 1)
        gemm_body<false, true>(k_in, g_rW + 1 * (size_t)HID * HID, bk, g_K);
    else
        gemm_body<false, true>(v_in, g_rW + 2 * (size_t)HID * HID, bv, g_V);
}

__global__ __launch_bounds__(512, 1) void gemm_out(
    const float* __restrict__ bias, float* __restrict__ C)
{
    gemm_body<true, false>(g_X, g_rW + 3 * (size_t)HID * HID, bias, C);
}

// =====================================================================
// Fused MMA attention (R14, proven): cp.async staging, RED scatter,
// dual-accumulator w1/w2. block = (32 q, h, b), 512 threads.
// =====================================================================
constexpr int OFF_P  = 2176;
constexpr int OFF_KV = 6400;
constexpr int OFF_S  = 24832;
constexpr int OFF_F  = 41344;
constexpr int SMF_TOTAL = OFF_F + (32 * 528) / 4;       // 45568 floats
constexpr size_t SMF_BYTES = (size_t)SMF_TOTAL * 4;     // 182,272 B

__global__ __launch_bounds__(512) void attn_fused_mma()
{
    extern __shared__ float smem[];
    float* sQ  = smem;                 // [32][68]
    float* sP  = smem + OFF_P;         // [32][132]
    float* sSb = smem;                 // [32][136] union
    float* sKV = smem + OFF_KV;
    float* sS  = smem + OFF_S;         // [32][516]
    unsigned char* sFb = reinterpret_cast<unsigned char*>(smem + OFF_F);

    const uint32_t sbase = smem_u32(smem);
    const uint32_t sQa  = sbase;
    const uint32_t sKVa = sbase + OFF_KV * 4;
    const uint32_t sFa  = sbase + OFF_F * 4;

    const int tid  = threadIdx.x;
    const int lane = tid & 31;
    const int warp = tid >> 5;
    const int g    = lane >> 2;
    const int t    = lane & 3;
    const int mh   = warp >> 3;        // 0..1
    const int wg   = warp & 7;         // 0..7
    const int mr   = mh * 16;
    const int q0   = blockIdx.x * 32;
    const int h    = blockIdx.y;
    const int b    = blockIdx.z;

    const float* gKb = g_K + (size_t)(b * L) * HID + h * HD;
    const float* gVb = g_V + (size_t)(b * L) * HID + h * HD;

    // ---------- stage 0: cp.async Q, table_k, fm ----------
    {
        const int q = tid >> 4, seg = tid & 15;
        CP_ASYNC16(sQa + (uint32_t)(q * 68 + seg * 4) * 4,
                   g_Q + (size_t)(b * L + q0 + q) * HID + h * HD + seg * 4);
    }
    for (int i = tid; i < (136 * 68) / 4; i += 512)
        CP_ASYNC16(sKVa + (uint32_t)i * 16, g_tk + i * 4);
    for (int i = tid; i < 32 * 32; i += 512) {
        const int q = i >> 5, seg = i & 31;
        CP_ASYNC16(sFa + (uint32_t)(q * 528 + seg * 16),
                   g_fmb + (size_t)(b * L + q0 + q) * L + seg * 16);
    }
    CP_COMMIT();
    CP_WAIT0();
    __syncthreads();

    // ---------- Q fragments into registers ----------
    float qf[8][4];
#pragma unroll
    for (int ks = 0; ks < 8; ks++) {
        const int kb = ks * 8;
        qf[ks][0] = sQ[(mr + g    ) * 68 + kb + t];
        qf[ks][1] = sQ[(mr + g + 8) * 68 + kb + t];
        qf[ks][2] = sQ[(mr + g    ) * 68 + kb + t + 4];
        qf[ks][3] = sQ[(mr + g + 8) * 68 + kb + t + 4];
    }

    // ---------- P[32][129] = Q @ table_k^T ----------
#pragma unroll
    for (int j = 0; j < 3; j++) {
        const int n8 = wg + 8 * j;
        if (n8 > 16) break;
        const int nb = n8 * 8;
        float acc[4] = {0.f, 0.f, 0.f, 0.f};
#pragma unroll
        for (int ks = 0; ks < 8; ks++) {
            const int kb = ks * 8;
            float bb[2];
            bb[0] = sKV[(nb + g) * 68 + kb + t];
            bb[1] = sKV[(nb + g) * 68 + kb + t + 4];
            mma_tf32(acc, qf[ks], bb);
        }
        const int c0 = nb + 2 * t;
        if (c0 < TAB) {
            sP[(mr + g    ) * 132 + c0] = acc[0];
            sP[(mr + g + 8) * 132 + c0] = acc[2];
        }
        if (c0 + 1 < TAB) {
            sP[(mr + g    ) * 132 + c0 + 1] = acc[1];
            sP[(mr + g + 8) * 132 + c0 + 1] = acc[3];
        }
    }
    __syncthreads();   // table_k reads complete

    // ---------- issue K tile 0 ----------
#pragma unroll
    for (int j = 0; j < 4; j++) {
        const int idx = tid + 512 * j, row = idx >> 4, seg = idx & 15;
        CP_ASYNC16(sKVa + (uint32_t)(row * 68 + seg * 4) * 4,
                   gKb + (size_t)row * HID + seg * 4);
    }
    CP_COMMIT();

    // ---------- scores: 4 K-tiles of 128, double-buffered ----------
#pragma unroll 1
    for (int kt = 0; kt < 4; kt++) {
        if (kt < 3) {
            const uint32_t dstb = sKVa + (uint32_t)(((kt + 1) & 1) * 8704) * 4;
#pragma unroll
            for (int j = 0; j < 4; j++) {
                const int idx = tid + 512 * j, row = idx >> 4, seg = idx & 15;
                CP_ASYNC16(dstb + (uint32_t)(row * 68 + seg * 4) * 4,
                           gKb + (size_t)((kt + 1) * 128 + row) * HID + seg * 4);
            }
            CP_COMMIT();
            CP_WAIT1();
        } else {
            CP_WAIT0();
        }
        __syncthreads();

        const float* Kb = sKV + (kt & 1) * 8704;
#pragma unroll
        for (int jj = 0; jj < 2; jj++) {
            const int nb = (wg * 2 + jj) * 8;
            float acc[4] = {0.f, 0.f, 0.f, 0.f};
#pragma unroll
            for (int ks = 0; ks < 8; ks++) {
                const int kb = ks * 8;
                float bb[2];
                bb[0] = Kb[(nb + g) * 68 + kb + t];
                bb[1] = Kb[(nb + g) * 68 + kb + t + 4];
                mma_tf32(acc, qf[ks], bb);
            }
            const int row0 = mr + g, row1 = row0 + 8;
            const int kc = kt * 128 + nb + 2 * t;
            const int t00 = sFb[row0 * 528 + kc], t01 = sFb[row0 * 528 + kc + 1];
            const int t10 = sFb[row1 * 528 + kc], t11 = sFb[row1 * 528 + kc + 1];
            sS[row0 * 516 + kc    ] = (acc[0] + sP[row0 * 132 + t00]) * 0.125f;
            sS[row0 * 516 + kc + 1] = (acc[1] + sP[row0 * 132 + t01]) * 0.125f;
            sS[row1 * 516 + kc    ] = (acc[2] + sP[row1 * 132 + t10]) * 0.125f;
            sS[row1 * 516 + kc + 1] = (acc[3] + sP[row1 * 132 + t11]) * 0.125f;
        }
        __syncthreads();
    }

    // ---------- issue V tile 0 (hides under softmax) ----------
#pragma unroll
    for (int j = 0; j < 4; j++) {
        const int idx = tid + 512 * j, row = idx >> 4, seg = idx & 15;
        CP_ASYNC16(sKVa + (uint32_t)(row * 72 + seg * 4) * 4,
                   gVb + (size_t)row * HID + seg * 4);
    }
    CP_COMMIT();

    // ---------- softmax (16 warps x 2 rows) ----------
    for (int r = warp * 2; r < warp * 2 + 2; r++) {
        float* row = sS + r * 516;
        float m = -1e30f;
#pragma unroll
        for (int i = 0; i < 16; i++) m = fmaxf(m, row[lane + 32 * i]);
#pragma unroll
        for (int o = 16; o > 0; o >>= 1) m = fmaxf(m, __shfl_xor_sync(0xffffffffu, m, o));
        float e[16];
        float s = 0.f;
#pragma unroll
        for (int i = 0; i < 16; i++) {
            e[i] = __expf(row[lane + 32 * i] - m);
            s += e[i];
        }
#pragma unroll
        for (int o = 16; o > 0; o >>= 1) s += __shfl_xor_sync(0xffffffffu, s, o);
        const float inv = 1.f / s;
#pragma unroll
        for (int i = 0; i < 16; i++) row[lane + 32 * i] = tf32r(e[i] * inv);
    }
    for (int i = tid; i < 32 * 136; i += 512) sSb[i] = 0.f;
    CP_WAIT0();
    __syncthreads();

    // ---------- w1 = attn @ V: 4 V-tiles of 128, double-buffered ----------
    const int nbw = wg * 8;
    float acc1a[4] = {0.f, 0.f, 0.f, 0.f};
    float acc1b[4] = {0.f, 0.f, 0.f, 0.f};
#pragma unroll 1
    for (int vt = 0; vt < 4; vt++) {
        if (vt < 3) {
            const uint32_t dstb = sKVa + (uint32_t)(((vt + 1) & 1) * 9216) * 4;
#pragma unroll
            for (int j = 0; j < 4; j++) {
                const int idx = tid + 512 * j, row = idx >> 4, seg = idx & 15;
                CP_ASYNC16(dstb + (uint32_t)(row * 72 + seg * 4) * 4,
                           gVb + (size_t)((vt + 1) * 128 + row) * HID + seg * 4);
            }
            CP_COMMIT();
            CP_WAIT1();
        } else {
            CP_WAIT0();
        }
        __syncthreads();

        const float* Vb = sKV + (vt & 1) * 9216;
        const int cb = vt * 128;
#pragma unroll
        for (int ks = 0; ks < 16; ks += 2) {
            {
                const int kb = ks * 8;
                float a[4], bb[2];
                a[0] = sS[(mr + g    ) * 516 + cb + kb + t];
                a[1] = sS[(mr + g + 8) * 516 + cb + kb + t];
                a[2] = sS[(mr + g    ) * 516 + cb + kb + t + 4];
                a[3] = sS[(mr + g + 8) * 516 + cb + kb + t + 4];
                bb[0] = Vb[(kb + t    ) * 72 + nbw + g];
                bb[1] = Vb[(kb + t + 4) * 72 + nbw + g];
                mma_tf32(acc1a, a, bb);
            }
            {
                const int kb = (ks + 1) * 8;
                float a[4], bb[2];
                a[0] = sS[(mr + g    ) * 516 + cb + kb + t];
                a[1] = sS[(mr + g + 8) * 516 + cb + kb + t];
                a[2] = sS[(mr + g    ) * 516 + cb + kb + t + 4];
                a[3] = sS[(mr + g + 8) * 516 + cb + kb + t + 4];
                bb[0] = Vb[(kb + t    ) * 72 + nbw + g];
                bb[1] = Vb[(kb + t + 4) * 72 + nbw + g];
                mma_tf32(acc1b, a, bb);
            }
        }
        __syncthreads();
    }

    // ---------- bucket scatter (RED) + stage table_v ----------
    {
        const int q  = tid >> 4;
        const int kg = tid & 15;
        const unsigned char* fr = sFb + q * 528;
        const float* ar = sS + q * 516;
        float* sbq = sSb + q * 136;
#pragma unroll 4
        for (int i = 0; i < 32; i++) {
            const int k = i * 16 + kg;
            atomicAdd(&sbq[fr[k]], ar[k]);
        }
    }
    for (int i = tid; i < (136 * 72) / 4; i += 512)
        CP_ASYNC16(sKVa + (uint32_t)i * 16, g_tv + i * 4);
    CP_COMMIT();
    CP_WAIT0();
    __syncthreads();

    // ---------- w2 = buckets @ table_v (17 k-steps, dual accumulators) ----------
    float acc2a[4] = {0.f, 0.f, 0.f, 0.f};
    float acc2b[4] = {0.f, 0.f, 0.f, 0.f};
#pragma unroll
    for (int ks = 0; ks < 17; ks++) {
        const int kb = ks * 8;
        float a[4], bb[2];
        a[0] = tf32r(sSb[(mr + g    ) * 136 + kb + t]);
        a[1] = tf32r(sSb[(mr + g + 8) * 136 + kb + t]);
        a[2] = tf32r(sSb[(mr + g    ) * 136 + kb + t + 4]);
        a[3] = tf32r(sSb[(mr + g + 8) * 136 + kb + t + 4]);
        bb[0] = sKV[(kb + t    ) * 72 + nbw + g];
        bb[1] = sKV[(kb + t + 4) * 72 + nbw + g];
        if (ks & 1) mma_tf32(acc2b, a, bb);
        else        mma_tf32(acc2a, a, bb);
    }

    // ---------- store (tf32-rounded for gemm_out's cp.async A path) ----------
    {
        const int row0 = mr + g;
        const int col  = nbw + 2 * t;
        float2 o0 = make_float2(tf32r(acc1a[0] + acc1b[0] + acc2a[0] + acc2b[0]),
                                tf32r(acc1a[1] + acc1b[1] + acc2a[1] + acc2b[1]));
        float2 o1 = make_float2(tf32r(acc1a[2] + acc1b[2] + acc2a[2] + acc2b[2]),
                                tf32r(acc1a[3] + acc1b[3] + acc2a[3] + acc2b[3]));
        *reinterpret_cast<float2*>(
            g_X + (size_t)(b * L + q0 + row0) * HID + h * HD + col) = o0;
        *reinterpret_cast<float2*>(
            g_X + (size_t)(b * L + q0 + row0 + 8) * HID + h * HD + col) = o1;
    }
}

// =====================================================================
// launch
// =====================================================================
extern "C" void kernel_launch(void* const* d_in, const int* in_sizes, int n_in,
                              void* d_out, int out_size)
{
    const float* query   = (const float*)d_in[0];
    const float* key     = (const float*)d_in[1];
    const float* value   = (const float*)d_in[2];
    const int*   fm      = (const int*)  d_in[3];
    const float* Wq      = (const float*)d_in[4];
    const float* bq      = (const float*)d_in[5];
    const float* Wk      = (const float*)d_in[6];
    const float* bk      = (const float*)d_in[7];
    const float* Wv      = (const float*)d_in[8];
    const float* bv      = (const float*)d_in[9];
    const float* Wo      = (const float*)d_in[10];
    const float* bo      = (const float*)d_in[11];
    const float* table_k = (const float*)d_in[12];
    const float* table_v = (const float*)d_in[13];
    float* out = (float*)d_out;

    cudaFuncSetAttribute(attn_fused_mma,
                         cudaFuncAttributeMaxDynamicSharedMemorySize, (int)SMF_BYTES);
    cudaFuncSetAttribute(gemm_qkv,
                         cudaFuncAttributeMaxDynamicSharedMemorySize, (int)GEMM_SMEM);
    cudaFuncSetAttribute(gemm_out,
                         cudaFuncAttributeMaxDynamicSharedMemorySize, (int)GEMM_SMEM);

    prep_kernel<<<2049 + 4096, 256>>>(fm, table_k, table_v, Wq, Wk, Wv, Wo);

    const dim3 gqkv(HID / 256, BL / 128, 3);  // (4, 32, 3)
    gemm_qkv<<<gqkv, 512, GEMM_SMEM>>>(query, key, value, bq, bk, bv);

    const dim3 gattn(L / 32, H, B);  // (16, 16, 8)
    attn_fused_mma<<<gattn, 512, SMF_BYTES>>>();

    const dim3 gout(HID / 256, BL / 128);  // (4, 32)
    gemm_out<<<gout, 512, GEMM_SMEM>>>(bo, out);
}

// round 16
// speedup vs baseline: 1.0955x; 1.0028x over previous
#include <cuda_runtime.h>
#include <cstdint>

// ---------------- problem constants ----------------
constexpr int B    = 8;
constexpr int L    = 512;
constexpr int HID  = 1024;
constexpr int H    = 16;
constexpr int HD   = 64;     // head dim
constexpr int TAB  = 129;    // 2*64+1 relative-position table rows
constexpr int BL   = B * L;  // 4096

// ---------------- device scratch ----------------
__device__ float g_Q[BL * HID];
__device__ float g_K[BL * HID];
__device__ float g_V[BL * HID];
__device__ float g_X[BL * HID];                 // w1+w2 merged (tf32-rounded)
__device__ float g_rW[4 * HID * HID];           // pre-rounded Wq,Wk,Wv,Wo
__device__ unsigned char g_fmb[(size_t)B * L * L];  // final_mat as uchar (2 MB)
__device__ float g_tk[136 * 68];                // table_k tf32-rounded, padded
__device__ float g_tv[136 * 72];                // table_v tf32-rounded, padded

// =====================================================================
// tf32 helpers
// =====================================================================
__device__ __forceinline__ float tf32r(float x) {
    unsigned y;
    asm("cvt.rna.tf32.f32 %0, %1;" : "=r"(y) : "f"(x));
    return __uint_as_float(y);
}

__device__ __forceinline__ float4 tf32r4(float4 v) {
    return make_float4(tf32r(v.x), tf32r(v.y), tf32r(v.z), tf32r(v.w));
}

__device__ __forceinline__ void mma_tf32(float d[4], const float a[4], const float b[2]) {
    unsigned const* A = reinterpret_cast<unsigned const*>(a);
    unsigned const* Bp = reinterpret_cast<unsigned const*>(b);
    asm volatile(
        "mma.sync.aligned.m16n8k8.row.col.f32.tf32.tf32.f32 "
        "{%0,%1,%2,%3}, {%4,%5,%6,%7}, {%8,%9}, {%0,%1,%2,%3};"
        : "+f"(d[0]), "+f"(d[1]), "+f"(d[2]), "+f"(d[3])
        : "r"(A[0]), "r"(A[1]), "r"(A[2]), "r"(A[3]),
          "r"(Bp[0]), "r"(Bp[1]));
}

// ---------------- cp.async helpers ----------------
__device__ __forceinline__ uint32_t smem_u32(const void* p) {
    uint32_t a;
    asm("{ .reg .u64 t; cvta.to.shared.u64 t, %1; cvt.u32.u64 %0, t; }"
        : "=r"(a) : "l"(p));
    return a;
}
#define CP_ASYNC16(dst, src) \
    asm volatile("cp.async.cg.shared.global [%0], [%1], 16;" \
                 :: "r"(dst), "l"(src) : "memory")
#define CP_COMMIT() asm volatile("cp.async.commit_group;" ::: "memory")
#define CP_WAIT0()  asm volatile("cp.async.wait_group 0;" ::: "memory")
#define CP_WAIT1()  asm volatile("cp.async.wait_group 1;" ::: "memory")

// =====================================================================
// Prep kernel: pack final_mat -> uchar; round+pad tables; round W's.
// =====================================================================
__global__ __launch_bounds__(256) void prep_kernel(
    const int* __restrict__ fm,
    const float* __restrict__ tk, const float* __restrict__ tv,
    const float* __restrict__ Wq, const float* __restrict__ Wk,
    const float* __restrict__ Wv, const float* __restrict__ Wo)
{
    const int bid = blockIdx.x;
    if (bid < 2048) {
        const int idx = bid * 1024 + threadIdx.x * 4;
        const int4 v = *reinterpret_cast<const int4*>(fm + idx);
        *reinterpret_cast<uchar4*>(g_fmb + idx) =
            make_uchar4((unsigned char)v.x, (unsigned char)v.y,
                        (unsigned char)v.z, (unsigned char)v.w);
    } else if (bid == 2048) {
        for (int i = threadIdx.x; i < 136 * 68; i += 256) {
            const int r = i / 68, c = i - r * 68;
            g_tk[i] = (r < TAB && c < 64) ? tf32r(tk[r * 64 + c]) : 0.f;
        }
        for (int i = threadIdx.x; i < 136 * 72; i += 256) {
            const int r = i / 72, c = i - r * 72;
            g_tv[i] = (r < TAB && c < 64) ? tf32r(tv[r * 64 + c]) : 0.f;
        }
    } else {
        const int r = bid - 2049;           // 0..4095
        const int w = r >> 10;              // matrix index
        const float* src = (w == 0) ? Wq : (w == 1) ? Wk : (w == 2) ? Wv : Wo;
        const int idx = (r & 1023) * 1024 + threadIdx.x * 4;
        float4 v = *reinterpret_cast<const float4*>(src + idx);
        *reinterpret_cast<float4*>(g_rW + (size_t)w * HID * HID + idx) = tf32r4(v);
    }
}

// =====================================================================
// GEMM v6 (R15, proven): BK=32, 3-stage cp.async pipeline.
// =====================================================================
constexpr int BKS = 36;
constexpr int GA  = 128 * BKS;
constexpr int GB  = 256 * BKS;
constexpr size_t GEMM_SMEM = (size_t)3 * (GA + GB) * 4;  // 165,888 B
constexpr int NKT = HID / 32;

template <bool A_PRE, bool ROUND>
__device__ __forceinline__ void gemm_body(
    const float* __restrict__ A, const float* __restrict__ rW,
    const float* __restrict__ bias, float* __restrict__ C)
{
    extern __shared__ float dsm[];
    const int tid  = threadIdx.x;
    const int m0   = blockIdx.y * 128;
    const int n0   = blockIdx.x * 256;
    const int lane = tid & 31;
    const int g    = lane >> 2;
    const int t    = lane & 3;
    const int warp = tid >> 5;
    const int wm   = warp >> 2;
    const int wn   = warp & 3;

    const int lrow = tid >> 3;
    const int lseg = (tid & 7) * 4;
    const float* ApS = A  + (size_t)(m0 + lrow) * HID + lseg;
    const float* BpS = rW + (size_t)(n0 + lrow) * HID + lseg;

    const uint32_t sb = smem_u32(dsm);
    const uint32_t aO = (uint32_t)(lrow * BKS + lseg) * 4;
    const uint32_t bO = (uint32_t)(3 * GA + lrow * BKS + lseg) * 4;

    float acc[2][8][4];
#pragma unroll
    for (int i = 0; i < 2; i++)
#pragma unroll
        for (int j = 0; j < 8; j++)
#pragma unroll
            for (int r = 0; r < 4; r++) acc[i][j][r] = 0.f;

    float4 pa[2];
    if (A_PRE) {
#pragma unroll
        for (int j = 0; j < 2; j++)
            CP_ASYNC16(sb + aO + (uint32_t)(64 * j * BKS) * 4,
                       ApS + (size_t)(64 * j) * HID);
    } else {
#pragma unroll
        for (int j = 0; j < 2; j++) {
            pa[j] = *reinterpret_cast<const float4*>(ApS + (size_t)(64 * j) * HID);
            *reinterpret_cast<float4*>(dsm + (lrow + 64 * j) * BKS + lseg) = tf32r4(pa[j]);
        }
    }
#pragma unroll
    for (int j = 0; j < 4; j++)
        CP_ASYNC16(sb + bO + (uint32_t)(64 * j * BKS) * 4,
                   BpS + (size_t)(64 * j) * HID);
    CP_COMMIT();

    if (A_PRE) {
#pragma unroll
        for (int j = 0; j < 2; j++)
            CP_ASYNC16(sb + aO + (uint32_t)(GA + 64 * j * BKS) * 4,
                       ApS + (size_t)(64 * j) * HID + 32);
    }
#pragma unroll
    for (int j = 0; j < 4; j++)
        CP_ASYNC16(sb + bO + (uint32_t)(GB + 64 * j * BKS) * 4,
                   BpS + (size_t)(64 * j) * HID + 32);
    CP_COMMIT();
    if (!A_PRE) {
#pragma unroll
        for (int j = 0; j < 2; j++)
            pa[j] = *reinterpret_cast<const float4*>(ApS + (size_t)(64 * j) * HID + 32);
    }

    for (int kt = 0; kt < NKT; kt++) {
        CP_WAIT1();
        __syncthreads();

        const int kn = kt + 2;
        if (kn < NKT) {
            const int k0 = kn * 32;
            const uint32_t s3 = (uint32_t)(kn % 3);
            if (A_PRE) {
#pragma unroll
                for (int j = 0; j < 2; j++)
                    CP_ASYNC16(sb + aO + (s3 * GA + (uint32_t)(64 * j * BKS)) * 4,
                               ApS + (size_t)(64 * j) * HID + k0);
            }
#pragma unroll
            for (int j = 0; j < 4; j++)
                CP_ASYNC16(sb + bO + (s3 * GB + (uint32_t)(64 * j * BKS)) * 4,
                           BpS + (size_t)(64 * j) * HID + k0);
        }
        CP_COMMIT();

        const float* As = dsm + (kt % 3) * GA;
        const float* Bs = dsm + 3 * GA + (kt % 3) * GB;
#pragma unroll
        for (int ks = 0; ks < 4; ks++) {
            const int kc = ks * 8 + t;
            float afr[2][4], bfr[8][2];
#pragma unroll
            for (int mt = 0; mt < 2; mt++) {
                const int r = wm * 32 + mt * 16 + g;
                afr[mt][0] = As[(r    ) * BKS + kc];
                afr[mt][1] = As[(r + 8) * BKS + kc];
                afr[mt][2] = As[(r    ) * BKS + kc + 4];
                afr[mt][3] = As[(r + 8) * BKS + kc + 4];
            }
#pragma unroll
            for (int nt = 0; nt < 8; nt++) {
                const int n = wn * 64 + nt * 8 + g;
                bfr[nt][0] = Bs[n * BKS + kc];
                bfr[nt][1] = Bs[n * BKS + kc + 4];
            }
#pragma unroll
            for (int mt = 0; mt < 2; mt++)
#pragma unroll
                for (int nt = 0; nt < 8; nt++)
                    mma_tf32(acc[mt][nt], afr[mt], bfr[nt]);
        }

        if (!A_PRE && kt + 1 < NKT) {
            float* ad = dsm + ((kt + 1) % 3) * GA;
#pragma unroll
            for (int j = 0; j < 2; j++)
                *reinterpret_cast<float4*>(ad + (lrow + 64 * j) * BKS + lseg) = tf32r4(pa[j]);
            if (kt + 2 < NKT) {
#pragma unroll
                for (int j = 0; j < 2; j++)
                    pa[j] = *reinterpret_cast<const float4*>(
                        ApS + (size_t)(64 * j) * HID + (kt + 2) * 32);
            }
        }
    }

#pragma unroll
    for (int mt = 0; mt < 2; mt++) {
        const int row0 = m0 + wm * 32 + mt * 16 + g;
#pragma unroll
        for (int nt = 0; nt < 8; nt++) {
            const int col = n0 + wn * 64 + nt * 8 + 2 * t;
            const float b0 = bias[col], b1 = bias[col + 1];
            float* c0 = C + (size_t)row0 * HID + col;
            float* c1 = C + (size_t)(row0 + 8) * HID + col;
            if (ROUND) {
                c0[0] = tf32r(acc[mt][nt][0] + b0); c0[1] = tf32r(acc[mt][nt][1] + b1);
                c1[0] = tf32r(acc[mt][nt][2] + b0); c1[1] = tf32r(acc[mt][nt][3] + b1);
            } else {
                c0[0] = acc[mt][nt][0] + b0; c0[1] = acc[mt][nt][1] + b1;
                c1[0] = acc[mt][nt][2] + b0; c1[1] = acc[mt][nt][3] + b1;
            }
        }
    }
}

__global__ __launch_bounds__(512, 1) void gemm_qkv(
    const float* __restrict__ q_in, const float* __restrict__ k_in,
    const float* __restrict__ v_in,
    const float* __restrict__ bq, const float* __restrict__ bk,
    const float* __restrict__ bv)
{
    if (blockIdx.z == 0)
        gemm_body<false, true>(q_in, g_rW + 0 * (size_t)HID * HID, bq, g_Q);
    else if (blockIdx.z == 1)
        gemm_body<false, true>(k_in, g_rW + 1 * (size_t)HID * HID, bk, g_K);
    else
        gemm_body<false, true>(v_in, g_rW + 2 * (size_t)HID * HID, bv, g_V);
}

__global__ __launch_bounds__(512, 1) void gemm_out(
    const float* __restrict__ bias, float* __restrict__ C)
{
    gemm_body<true, false>(g_X, g_rW + 3 * (size_t)HID * HID, bias, C);
}

// =====================================================================
// Fused MMA attention v7: R14 + INTERLEAVED MMA chains in P and scores
// (ks outer, tile inner -> 2-3 way tensor ILP; arithmetic bit-identical).
// =====================================================================
constexpr int OFF_P  = 2176;
constexpr int OFF_KV = 6400;
constexpr int OFF_S  = 24832;
constexpr int OFF_F  = 41344;
constexpr int SMF_TOTAL = OFF_F + (32 * 528) / 4;       // 45568 floats
constexpr size_t SMF_BYTES = (size_t)SMF_TOTAL * 4;     // 182,272 B

__global__ __launch_bounds__(512) void attn_fused_mma()
{
    extern __shared__ float smem[];
    float* sQ  = smem;                 // [32][68]
    float* sP  = smem + OFF_P;         // [32][132]
    float* sSb = smem;                 // [32][136] union
    float* sKV = smem + OFF_KV;
    float* sS  = smem + OFF_S;         // [32][516]
    unsigned char* sFb = reinterpret_cast<unsigned char*>(smem + OFF_F);

    const uint32_t sbase = smem_u32(smem);
    const uint32_t sQa  = sbase;
    const uint32_t sKVa = sbase + OFF_KV * 4;
    const uint32_t sFa  = sbase + OFF_F * 4;

    const int tid  = threadIdx.x;
    const int lane = tid & 31;
    const int warp = tid >> 5;
    const int g    = lane >> 2;
    const int t    = lane & 3;
    const int mh   = warp >> 3;        // 0..1
    const int wg   = warp & 7;         // 0..7
    const int mr   = mh * 16;
    const int q0   = blockIdx.x * 32;
    const int h    = blockIdx.y;
    const int b    = blockIdx.z;

    const float* gKb = g_K + (size_t)(b * L) * HID + h * HD;
    const float* gVb = g_V + (size_t)(b * L) * HID + h * HD;

    // ---------- stage 0: cp.async Q, table_k, fm ----------
    {
        const int q = tid >> 4, seg = tid & 15;
        CP_ASYNC16(sQa + (uint32_t)(q * 68 + seg * 4) * 4,
                   g_Q + (size_t)(b * L + q0 + q) * HID + h * HD + seg * 4);
    }
    for (int i = tid; i < (136 * 68) / 4; i += 512)
        CP_ASYNC16(sKVa + (uint32_t)i * 16, g_tk + i * 4);
    for (int i = tid; i < 32 * 32; i += 512) {
        const int q = i >> 5, seg = i & 31;
        CP_ASYNC16(sFa + (uint32_t)(q * 528 + seg * 16),
                   g_fmb + (size_t)(b * L + q0 + q) * L + seg * 16);
    }
    CP_COMMIT();
    CP_WAIT0();
    __syncthreads();

    // ---------- Q fragments into registers ----------
    float qf[8][4];
#pragma unroll
    for (int ks = 0; ks < 8; ks++) {
        const int kb = ks * 8;
        qf[ks][0] = sQ[(mr + g    ) * 68 + kb + t];
        qf[ks][1] = sQ[(mr + g + 8) * 68 + kb + t];
        qf[ks][2] = sQ[(mr + g    ) * 68 + kb + t + 4];
        qf[ks][3] = sQ[(mr + g + 8) * 68 + kb + t + 4];
    }

    // ---------- P[32][129] = Q @ table_k^T (interleaved 2-way + tail) ----------
    {
        float pacc[2][4];
#pragma unroll
        for (int j = 0; j < 2; j++)
#pragma unroll
            for (int r = 0; r < 4; r++) pacc[j][r] = 0.f;
#pragma unroll
        for (int ks = 0; ks < 8; ks++) {
            const int kb = ks * 8;
#pragma unroll
            for (int j = 0; j < 2; j++) {
                const int nb = (wg + 8 * j) * 8;
                float bb[2];
                bb[0] = sKV[(nb + g) * 68 + kb + t];
                bb[1] = sKV[(nb + g) * 68 + kb + t + 4];
                mma_tf32(pacc[j], qf[ks], bb);
            }
        }
#pragma unroll
        for (int j = 0; j < 2; j++) {
            const int nb = (wg + 8 * j) * 8;
            const int c0 = nb + 2 * t;
            sP[(mr + g    ) * 132 + c0]     = pacc[j][0];
            sP[(mr + g    ) * 132 + c0 + 1] = pacc[j][1];
            sP[(mr + g + 8) * 132 + c0]     = pacc[j][2];
            sP[(mr + g + 8) * 132 + c0 + 1] = pacc[j][3];
        }
        // tail tile n8 = 16 (columns 128): only wg == 0
        if (wg == 0) {
            float tacc[4] = {0.f, 0.f, 0.f, 0.f};
#pragma unroll
            for (int ks = 0; ks < 8; ks++) {
                const int kb = ks * 8;
                float bb[2];
                bb[0] = sKV[(128 + g) * 68 + kb + t];
                bb[1] = sKV[(128 + g) * 68 + kb + t + 4];
                mma_tf32(tacc, qf[ks], bb);
            }
            const int c0 = 128 + 2 * t;
            if (c0 < TAB) {
                sP[(mr + g    ) * 132 + c0] = tacc[0];
                sP[(mr + g + 8) * 132 + c0] = tacc[2];
            }
            if (c0 + 1 < TAB) {
                sP[(mr + g    ) * 132 + c0 + 1] = tacc[1];
                sP[(mr + g + 8) * 132 + c0 + 1] = tacc[3];
            }
        }
    }
    __syncthreads();   // table_k reads complete

    // ---------- issue K tile 0 ----------
#pragma unroll
    for (int j = 0; j < 4; j++) {
        const int idx = tid + 512 * j, row = idx >> 4, seg = idx & 15;
        CP_ASYNC16(sKVa + (uint32_t)(row * 68 + seg * 4) * 4,
                   gKb + (size_t)row * HID + seg * 4);
    }
    CP_COMMIT();

    // ---------- scores: 4 K-tiles of 128, double-buffered, 2-way ILP ----------
#pragma unroll 1
    for (int kt = 0; kt < 4; kt++) {
        if (kt < 3) {
            const uint32_t dstb = sKVa + (uint32_t)(((kt + 1) & 1) * 8704) * 4;
#pragma unroll
            for (int j = 0; j < 4; j++) {
                const int idx = tid + 512 * j, row = idx >> 4, seg = idx & 15;
                CP_ASYNC16(dstb + (uint32_t)(row * 68 + seg * 4) * 4,
                           gKb + (size_t)((kt + 1) * 128 + row) * HID + seg * 4);
            }
            CP_COMMIT();
            CP_WAIT1();
        } else {
            CP_WAIT0();
        }
        __syncthreads();

        const float* Kb = sKV + (kt & 1) * 8704;
        float sacc[2][4];
#pragma unroll
        for (int j = 0; j < 2; j++)
#pragma unroll
            for (int r = 0; r < 4; r++) sacc[j][r] = 0.f;

#pragma unroll
        for (int ks = 0; ks < 8; ks++) {
            const int kb = ks * 8;
#pragma unroll
            for (int jj = 0; jj < 2; jj++) {
                const int nb = (wg * 2 + jj) * 8;
                float bb[2];
                bb[0] = Kb[(nb + g) * 68 + kb + t];
                bb[1] = Kb[(nb + g) * 68 + kb + t + 4];
                mma_tf32(sacc[jj], qf[ks], bb);
            }
        }

#pragma unroll
        for (int jj = 0; jj < 2; jj++) {
            const int nb = (wg * 2 + jj) * 8;
            const int row0 = mr + g, row1 = row0 + 8;
            const int kc = kt * 128 + nb + 2 * t;
            const int t00 = sFb[row0 * 528 + kc], t01 = sFb[row0 * 528 + kc + 1];
            const int t10 = sFb[row1 * 528 + kc], t11 = sFb[row1 * 528 + kc + 1];
            sS[row0 * 516 + kc    ] = (sacc[jj][0] + sP[row0 * 132 + t00]) * 0.125f;
            sS[row0 * 516 + kc + 1] = (sacc[jj][1] + sP[row0 * 132 + t01]) * 0.125f;
            sS[row1 * 516 + kc    ] = (sacc[jj][2] + sP[row1 * 132 + t10]) * 0.125f;
            sS[row1 * 516 + kc + 1] = (sacc[jj][3] + sP[row1 * 132 + t11]) * 0.125f;
        }
        __syncthreads();
    }

    // ---------- issue V tile 0 (hides under softmax) ----------
#pragma unroll
    for (int j = 0; j < 4; j++) {
        const int idx = tid + 512 * j, row = idx >> 4, seg = idx & 15;
        CP_ASYNC16(sKVa + (uint32_t)(row * 72 + seg * 4) * 4,
                   gVb + (size_t)row * HID + seg * 4);
    }
    CP_COMMIT();

    // ---------- softmax (16 warps x 2 rows) ----------
    for (int r = warp * 2; r < warp * 2 + 2; r++) {
        float* row = sS + r * 516;
        float m = -1e30f;
#pragma unroll
        for (int i = 0; i < 16; i++) m = fmaxf(m, row[lane + 32 * i]);
#pragma unroll
        for (int o = 16; o > 0; o >>= 1) m = fmaxf(m, __shfl_xor_sync(0xffffffffu, m, o));
        float e[16];
        float s = 0.f;
#pragma unroll
        for (int i = 0; i < 16; i++) {
            e[i] = __expf(row[lane + 32 * i] - m);
            s += e[i];
        }
#pragma unroll
        for (int o = 16; o > 0; o >>= 1) s += __shfl_xor_sync(0xffffffffu, s, o);
        const float inv = 1.f / s;
#pragma unroll
        for (int i = 0; i < 16; i++) row[lane + 32 * i] = tf32r(e[i] * inv);
    }
    for (int i = tid; i < 32 * 136; i += 512) sSb[i] = 0.f;
    CP_WAIT0();
    __syncthreads();

    // ---------- w1 = attn @ V: 4 V-tiles of 128, dual accumulators ----------
    const int nbw = wg * 8;
    float acc1a[4] = {0.f, 0.f, 0.f, 0.f};
    float acc1b[4] = {0.f, 0.f, 0.f, 0.f};
#pragma unroll 1
    for (int vt = 0; vt < 4; vt++) {
        if (vt < 3) {
            const uint32_t dstb = sKVa + (uint32_t)(((vt + 1) & 1) * 9216) * 4;
#pragma unroll
            for (int j = 0; j < 4; j++) {
                const int idx = tid + 512 * j, row = idx >> 4, seg = idx & 15;
                CP_ASYNC16(dstb + (uint32_t)(row * 72 + seg * 4) * 4,
                           gVb + (size_t)((vt + 1) * 128 + row) * HID + seg * 4);
            }
            CP_COMMIT();
            CP_WAIT1();
        } else {
            CP_WAIT0();
        }
        __syncthreads();

        const float* Vb = sKV + (vt & 1) * 9216;
        const int cb = vt * 128;
#pragma unroll
        for (int ks = 0; ks < 16; ks += 2) {
            {
                const int kb = ks * 8;
                float a[4], bb[2];
                a[0] = sS[(mr + g    ) * 516 + cb + kb + t];
                a[1] = sS[(mr + g + 8) * 516 + cb + kb + t];
                a[2] = sS[(mr + g    ) * 516 + cb + kb + t + 4];
                a[3] = sS[(mr + g + 8) * 516 + cb + kb + t + 4];
                bb[0] = Vb[(kb + t    ) * 72 + nbw + g];
                bb[1] = Vb[(kb + t + 4) * 72 + nbw + g];
                mma_tf32(acc1a, a, bb);
            }
            {
                const int kb = (ks + 1) * 8;
                float a[4], bb[2];
                a[0] = sS[(mr + g    ) * 516 + cb + kb + t];
                a[1] = sS[(mr + g + 8) * 516 + cb + kb + t];
                a[2] = sS[(mr + g    ) * 516 + cb + kb + t + 4];
                a[3] = sS[(mr + g + 8) * 516 + cb + kb + t + 4];
                bb[0] = Vb[(kb + t    ) * 72 + nbw + g];
                bb[1] = Vb[(kb + t + 4) * 72 + nbw + g];
                mma_tf32(acc1b, a, bb);
            }
        }
        __syncthreads();
    }

    // ---------- bucket scatter (RED) + stage table_v ----------
    {
        const int q  = tid >> 4;
        const int kg = tid & 15;
        const unsigned char* fr = sFb + q * 528;
        const float* ar = sS + q * 516;
        float* sbq = sSb + q * 136;
#pragma unroll 4
        for (int i = 0; i < 32; i++) {
            const int k = i * 16 + kg;
            atomicAdd(&sbq[fr[k]], ar[k]);
        }
    }
    for (int i = tid; i < (136 * 72) / 4; i += 512)
        CP_ASYNC16(sKVa + (uint32_t)i * 16, g_tv + i * 4);
    CP_COMMIT();
    CP_WAIT0();
    __syncthreads();

    // ---------- w2 = buckets @ table_v (17 k-steps, dual accumulators) ----------
    float acc2a[4] = {0.f, 0.f, 0.f, 0.f};
    float acc2b[4] = {0.f, 0.f, 0.f, 0.f};
#pragma unroll
    for (int ks = 0; ks < 17; ks++) {
        const int kb = ks * 8;
        float a[4], bb[2];
        a[0] = tf32r(sSb[(mr + g    ) * 136 + kb + t]);
        a[1] = tf32r(sSb[(mr + g + 8) * 136 + kb + t]);
        a[2] = tf32r(sSb[(mr + g    ) * 136 + kb + t + 4]);
        a[3] = tf32r(sSb[(mr + g + 8) * 136 + kb + t + 4]);
        bb[0] = sKV[(kb + t    ) * 72 + nbw + g];
        bb[1] = sKV[(kb + t + 4) * 72 + nbw + g];
        if (ks & 1) mma_tf32(acc2b, a, bb);
        else        mma_tf32(acc2a, a, bb);
    }

    // ---------- store (tf32-rounded for gemm_out's cp.async A path) ----------
    {
        const int row0 = mr + g;
        const int col  = nbw + 2 * t;
        float2 o0 = make_float2(tf32r(acc1a[0] + acc1b[0] + acc2a[0] + acc2b[0]),
                                tf32r(acc1a[1] + acc1b[1] + acc2a[1] + acc2b[1]));
        float2 o1 = make_float2(tf32r(acc1a[2] + acc1b[2] + acc2a[2] + acc2b[2]),
                                tf32r(acc1a[3] + acc1b[3] + acc2a[3] + acc2b[3]));
        *reinterpret_cast<float2*>(
            g_X + (size_t)(b * L + q0 + row0) * HID + h * HD + col) = o0;
        *reinterpret_cast<float2*>(
            g_X + (size_t)(b * L + q0 + row0 + 8) * HID + h * HD + col) = o1;
    }
}

// =====================================================================
// launch
// =====================================================================
extern "C" void kernel_launch(void* const* d_in, const int* in_sizes, int n_in,
                              void* d_out, int out_size)
{
    const float* query   = (const float*)d_in[0];
    const float* key     = (const float*)d_in[1];
    const float* value   = (const float*)d_in[2];
    const int*   fm      = (const int*)  d_in[3];
    const float* Wq      = (const float*)d_in[4];
    const float* bq      = (const float*)d_in[5];
    const float* Wk      = (const float*)d_in[6];
    const float* bk      = (const float*)d_in[7];
    const float* Wv      = (const float*)d_in[8];
    const float* bv      = (const float*)d_in[9];
    const float* Wo      = (const float*)d_in[10];
    const float* bo      = (const float*)d_in[11];
    const float* table_k = (const float*)d_in[12];
    const float* table_v = (const float*)d_in[13];
    float* out = (float*)d_out;

    cudaFuncSetAttribute(attn_fused_mma,
                         cudaFuncAttributeMaxDynamicSharedMemorySize, (int)SMF_BYTES);
    cudaFuncSetAttribute(gemm_qkv,
                         cudaFuncAttributeMaxDynamicSharedMemorySize, (int)GEMM_SMEM);
    cudaFuncSetAttribute(gemm_out,
                         cudaFuncAttributeMaxDynamicSharedMemorySize, (int)GEMM_SMEM);

    prep_kernel<<<2049 + 4096, 256>>>(fm, table_k, table_v, Wq, Wk, Wv, Wo);

    const dim3 gqkv(HID / 256, BL / 128, 3);  // (4, 32, 3)
    gemm_qkv<<<gqkv, 512, GEMM_SMEM>>>(query, key, value, bq, bk, bv);

    const dim3 gattn(L / 32, H, B);  // (16, 16, 8)
    attn_fused_mma<<<gattn, 512, SMF_BYTES>>>();

    const dim3 gout(HID / 256, BL / 128);  // (4, 32)
    gemm_out<<<gout, 512, GEMM_SMEM>>>(bo, out);
}

// round 17
// speedup vs baseline: 1.1145x; 1.0174x over previous
#include <cuda_runtime.h>
#include <cstdint>

// ---------------- problem constants ----------------
constexpr int B    = 8;
constexpr int L    = 512;
constexpr int HID  = 1024;
constexpr int H    = 16;
constexpr int HD   = 64;     // head dim
constexpr int TAB  = 129;    // 2*64+1 relative-position table rows
constexpr int BL   = B * L;  // 4096

// ---------------- device scratch ----------------
__device__ float g_Q[BL * HID];
__device__ float g_K[BL * HID];
__device__ float g_V[BL * HID];
__device__ float g_X[BL * HID];                 // w1+w2 merged (tf32-rounded)
__device__ float g_rW[4 * HID * HID];           // pre-rounded Wq,Wk,Wv,Wo
__device__ unsigned char g_fmb[(size_t)B * L * L];  // final_mat as uchar (2 MB)
__device__ float g_tk[136 * 68];                // table_k tf32-rounded, padded
__device__ float g_tv[136 * 72];                // table_v tf32-rounded, padded

// =====================================================================
// tf32 helpers
// =====================================================================
__device__ __forceinline__ float tf32r(float x) {
    unsigned y;
    asm("cvt.rna.tf32.f32 %0, %1;" : "=r"(y) : "f"(x));
    return __uint_as_float(y);
}

__device__ __forceinline__ float4 tf32r4(float4 v) {
    return make_float4(tf32r(v.x), tf32r(v.y), tf32r(v.z), tf32r(v.w));
}

__device__ __forceinline__ void mma_tf32(float d[4], const float a[4], const float b[2]) {
    unsigned const* A = reinterpret_cast<unsigned const*>(a);
    unsigned const* Bp = reinterpret_cast<unsigned const*>(b);
    asm volatile(
        "mma.sync.aligned.m16n8k8.row.col.f32.tf32.tf32.f32 "
        "{%0,%1,%2,%3}, {%4,%5,%6,%7}, {%8,%9}, {%0,%1,%2,%3};"
        : "+f"(d[0]), "+f"(d[1]), "+f"(d[2]), "+f"(d[3])
        : "r"(A[0]), "r"(A[1]), "r"(A[2]), "r"(A[3]),
          "r"(Bp[0]), "r"(Bp[1]));
}

// ---------------- cp.async helpers ----------------
__device__ __forceinline__ uint32_t smem_u32(const void* p) {
    uint32_t a;
    asm("{ .reg .u64 t; cvta.to.shared.u64 t, %1; cvt.u32.u64 %0, t; }"
        : "=r"(a) : "l"(p));
    return a;
}
#define CP_ASYNC16(dst, src) \
    asm volatile("cp.async.cg.shared.global [%0], [%1], 16;" \
                 :: "r"(dst), "l"(src) : "memory")
#define CP_COMMIT() asm volatile("cp.async.commit_group;" ::: "memory")
#define CP_WAIT0()  asm volatile("cp.async.wait_group 0;" ::: "memory")
#define CP_WAIT1()  asm volatile("cp.async.wait_group 1;" ::: "memory")

// =====================================================================
// Prep kernel: pack final_mat -> uchar; round+pad tables; round W's.
// =====================================================================
__global__ __launch_bounds__(256) void prep_kernel(
    const int* __restrict__ fm,
    const float* __restrict__ tk, const float* __restrict__ tv,
    const float* __restrict__ Wq, const float* __restrict__ Wk,
    const float* __restrict__ Wv, const float* __restrict__ Wo)
{
    const int bid = blockIdx.x;
    if (bid < 2048) {
        const int idx = bid * 1024 + threadIdx.x * 4;
        const int4 v = *reinterpret_cast<const int4*>(fm + idx);
        *reinterpret_cast<uchar4*>(g_fmb + idx) =
            make_uchar4((unsigned char)v.x, (unsigned char)v.y,
                        (unsigned char)v.z, (unsigned char)v.w);
    } else if (bid == 2048) {
        for (int i = threadIdx.x; i < 136 * 68; i += 256) {
            const int r = i / 68, c = i - r * 68;
            g_tk[i] = (r < TAB && c < 64) ? tf32r(tk[r * 64 + c]) : 0.f;
        }
        for (int i = threadIdx.x; i < 136 * 72; i += 256) {
            const int r = i / 72, c = i - r * 72;
            g_tv[i] = (r < TAB && c < 64) ? tf32r(tv[r * 64 + c]) : 0.f;
        }
    } else {
        const int r = bid - 2049;           // 0..4095
        const int w = r >> 10;              // matrix index
        const float* src = (w == 0) ? Wq : (w == 1) ? Wk : (w == 2) ? Wv : Wo;
        const int idx = (r & 1023) * 1024 + threadIdx.x * 4;
        float4 v = *reinterpret_cast<const float4*>(src + idx);
        *reinterpret_cast<float4*>(g_rW + (size_t)w * HID * HID + idx) = tf32r4(v);
    }
}

// =====================================================================
// GEMM v7: 128x128x32 tiles, 256 thr (8 warps: 4m x 2n, warp 32x64),
// 3-stage cp.async pipeline, 110.6 KB smem -> 2 BLOCKS/SM co-resident.
// =====================================================================
constexpr int BKS = 36;
constexpr int GA  = 128 * BKS;             // 4608 floats (A tile)
constexpr int GB  = 128 * BKS;             // 4608 floats (B tile)
constexpr size_t GEMM_SMEM = (size_t)3 * (GA + GB) * 4;  // 110,592 B
constexpr int NKT = HID / 32;              // 32 k-tiles

template <bool A_PRE, bool ROUND>
__device__ __forceinline__ void gemm_body(
    const float* __restrict__ A, const float* __restrict__ rW,
    const float* __restrict__ bias, float* __restrict__ C)
{
    extern __shared__ float dsm[];
    const int tid  = threadIdx.x;
    const int m0   = blockIdx.y * 128;
    const int n0   = blockIdx.x * 128;
    const int lane = tid & 31;
    const int g    = lane >> 2;
    const int t    = lane & 3;
    const int warp = tid >> 5;         // 0..7
    const int wm   = warp & 3;         // 0..3 (32 rows each)
    const int wn   = warp >> 2;        // 0..1 (64 cols each)

    // staging: 8 threads/row (float4 each), rows lrow+32*j, j=0..3
    const int lrow = tid >> 3;          // 0..31
    const int lseg = (tid & 7) * 4;
    const float* ApS = A  + (size_t)(m0 + lrow) * HID + lseg;
    const float* BpS = rW + (size_t)(n0 + lrow) * HID + lseg;

    const uint32_t sb = smem_u32(dsm);
    const uint32_t aO = (uint32_t)(lrow * BKS + lseg) * 4;
    const uint32_t bO = (uint32_t)(3 * GA + lrow * BKS + lseg) * 4;

    float acc[2][8][4];
#pragma unroll
    for (int i = 0; i < 2; i++)
#pragma unroll
        for (int j = 0; j < 8; j++)
#pragma unroll
            for (int r = 0; r < 4; r++) acc[i][j][r] = 0.f;

    // ---- prologue: tiles 0 and 1 ----
    float4 pa[4];
    if (A_PRE) {
#pragma unroll
        for (int j = 0; j < 4; j++)
            CP_ASYNC16(sb + aO + (uint32_t)(32 * j * BKS) * 4,
                       ApS + (size_t)(32 * j) * HID);
    } else {
#pragma unroll
        for (int j = 0; j < 4; j++) {
            pa[j] = *reinterpret_cast<const float4*>(ApS + (size_t)(32 * j) * HID);
            *reinterpret_cast<float4*>(dsm + (lrow + 32 * j) * BKS + lseg) = tf32r4(pa[j]);
        }
    }
#pragma unroll
    for (int j = 0; j < 4; j++)
        CP_ASYNC16(sb + bO + (uint32_t)(32 * j * BKS) * 4,
                   BpS + (size_t)(32 * j) * HID);
    CP_COMMIT();                           // group: tile 0

    if (A_PRE) {
#pragma unroll
        for (int j = 0; j < 4; j++)
            CP_ASYNC16(sb + aO + (uint32_t)(GA + 32 * j * BKS) * 4,
                       ApS + (size_t)(32 * j) * HID + 32);
    }
#pragma unroll
    for (int j = 0; j < 4; j++)
        CP_ASYNC16(sb + bO + (uint32_t)(GB + 32 * j * BKS) * 4,
                   BpS + (size_t)(32 * j) * HID + 32);
    CP_COMMIT();                           // group: tile 1
    if (!A_PRE) {
#pragma unroll
        for (int j = 0; j < 4; j++)
            pa[j] = *reinterpret_cast<const float4*>(ApS + (size_t)(32 * j) * HID + 32);
    }

    for (int kt = 0; kt < NKT; kt++) {
        CP_WAIT1();          // oldest pending (tile kt) landed
        __syncthreads();

        const int kn = kt + 2;
        if (kn < NKT) {
            const int k0 = kn * 32;
            const uint32_t s3 = (uint32_t)(kn % 3);
            if (A_PRE) {
#pragma unroll
                for (int j = 0; j < 4; j++)
                    CP_ASYNC16(sb + aO + (s3 * GA + (uint32_t)(32 * j * BKS)) * 4,
                               ApS + (size_t)(32 * j) * HID + k0);
            }
#pragma unroll
            for (int j = 0; j < 4; j++)
                CP_ASYNC16(sb + bO + (s3 * GB + (uint32_t)(32 * j * BKS)) * 4,
                           BpS + (size_t)(32 * j) * HID + k0);
        }
        CP_COMMIT();         // unconditional: exact group counting at tail

        const float* As = dsm + (A_PRE ? (kt % 3) : (kt & 1)) * GA;
        const float* Bs = dsm + 3 * GA + (kt % 3) * GB;
#pragma unroll
        for (int ks = 0; ks < 4; ks++) {
            const int kc = ks * 8 + t;
            float afr[2][4], bfr[8][2];
#pragma unroll
            for (int mt = 0; mt < 2; mt++) {
                const int r = wm * 32 + mt * 16 + g;
                afr[mt][0] = As[(r    ) * BKS + kc];
                afr[mt][1] = As[(r + 8) * BKS + kc];
                afr[mt][2] = As[(r    ) * BKS + kc + 4];
                afr[mt][3] = As[(r + 8) * BKS + kc + 4];
            }
#pragma unroll
            for (int nt = 0; nt < 8; nt++) {
                const int n = wn * 64 + nt * 8 + g;
                bfr[nt][0] = Bs[n * BKS + kc];
                bfr[nt][1] = Bs[n * BKS + kc + 4];
            }
#pragma unroll
            for (int mt = 0; mt < 2; mt++)
#pragma unroll
                for (int nt = 0; nt < 8; nt++)
                    mma_tf32(acc[mt][nt], afr[mt], bfr[nt]);
        }

        if (!A_PRE && kt + 1 < NKT) {
            float* ad = dsm + ((kt + 1) & 1) * GA;
#pragma unroll
            for (int j = 0; j < 4; j++)
                *reinterpret_cast<float4*>(ad + (lrow + 32 * j) * BKS + lseg) = tf32r4(pa[j]);
            if (kt + 2 < NKT) {
#pragma unroll
                for (int j = 0; j < 4; j++)
                    pa[j] = *reinterpret_cast<const float4*>(
                        ApS + (size_t)(32 * j) * HID + (kt + 2) * 32);
            }
        }
    }

#pragma unroll
    for (int mt = 0; mt < 2; mt++) {
        const int row0 = m0 + wm * 32 + mt * 16 + g;
#pragma unroll
        for (int nt = 0; nt < 8; nt++) {
            const int col = n0 + wn * 64 + nt * 8 + 2 * t;
            const float b0 = bias[col], b1 = bias[col + 1];
            float* c0 = C + (size_t)row0 * HID + col;
            float* c1 = C + (size_t)(row0 + 8) * HID + col;
            if (ROUND) {
                c0[0] = tf32r(acc[mt][nt][0] + b0); c0[1] = tf32r(acc[mt][nt][1] + b1);
                c1[0] = tf32r(acc[mt][nt][2] + b0); c1[1] = tf32r(acc[mt][nt][3] + b1);
            } else {
                c0[0] = acc[mt][nt][0] + b0; c0[1] = acc[mt][nt][1] + b1;
                c1[0] = acc[mt][nt][2] + b0; c1[1] = acc[mt][nt][3] + b1;
            }
        }
    }
}

__global__ __launch_bounds__(256, 2) void gemm_qkv(
    const float* __restrict__ q_in, const float* __restrict__ k_in,
    const float* __restrict__ v_in,
    const float* __restrict__ bq, const float* __restrict__ bk,
    const float* __restrict__ bv)
{
    if (blockIdx.z == 0)
        gemm_body<false, true>(q_in, g_rW + 0 * (size_t)HID * HID, bq, g_Q);
    else if (blockIdx.z == 1)
        gemm_body<false, true>(k_in, g_rW + 1 * (size_t)HID * HID, bk, g_K);
    else
        gemm_body<false, true>(v_in, g_rW + 2 * (size_t)HID * HID, bv, g_V);
}

__global__ __launch_bounds__(256, 2) void gemm_out(
    const float* __restrict__ bias, float* __restrict__ C)
{
    gemm_body<true, false>(g_X, g_rW + 3 * (size_t)HID * HID, bias, C);
}

// =====================================================================
// Fused MMA attention (R16, proven): cp.async staging, RED scatter,
// interleaved P/scores chains, dual-accumulator w1/w2.
// block = (32 q, h, b), 512 threads.
// =====================================================================
constexpr int OFF_P  = 2176;
constexpr int OFF_KV = 6400;
constexpr int OFF_S  = 24832;
constexpr int OFF_F  = 41344;
constexpr int SMF_TOTAL = OFF_F + (32 * 528) / 4;       // 45568 floats
constexpr size_t SMF_BYTES = (size_t)SMF_TOTAL * 4;     // 182,272 B

__global__ __launch_bounds__(512) void attn_fused_mma()
{
    extern __shared__ float smem[];
    float* sQ  = smem;                 // [32][68]
    float* sP  = smem + OFF_P;         // [32][132]
    float* sSb = smem;                 // [32][136] union
    float* sKV = smem + OFF_KV;
    float* sS  = smem + OFF_S;         // [32][516]
    unsigned char* sFb = reinterpret_cast<unsigned char*>(smem + OFF_F);

    const uint32_t sbase = smem_u32(smem);
    const uint32_t sQa  = sbase;
    const uint32_t sKVa = sbase + OFF_KV * 4;
    const uint32_t sFa  = sbase + OFF_F * 4;

    const int tid  = threadIdx.x;
    const int lane = tid & 31;
    const int warp = tid >> 5;
    const int g    = lane >> 2;
    const int t    = lane & 3;
    const int mh   = warp >> 3;        // 0..1
    const int wg   = warp & 7;         // 0..7
    const int mr   = mh * 16;
    const int q0   = blockIdx.x * 32;
    const int h    = blockIdx.y;
    const int b    = blockIdx.z;

    const float* gKb = g_K + (size_t)(b * L) * HID + h * HD;
    const float* gVb = g_V + (size_t)(b * L) * HID + h * HD;

    // ---------- stage 0: cp.async Q, table_k, fm ----------
    {
        const int q = tid >> 4, seg = tid & 15;
        CP_ASYNC16(sQa + (uint32_t)(q * 68 + seg * 4) * 4,
                   g_Q + (size_t)(b * L + q0 + q) * HID + h * HD + seg * 4);
    }
    for (int i = tid; i < (136 * 68) / 4; i += 512)
        CP_ASYNC16(sKVa + (uint32_t)i * 16, g_tk + i * 4);
    for (int i = tid; i < 32 * 32; i += 512) {
        const int q = i >> 5, seg = i & 31;
        CP_ASYNC16(sFa + (uint32_t)(q * 528 + seg * 16),
                   g_fmb + (size_t)(b * L + q0 + q) * L + seg * 16);
    }
    CP_COMMIT();
    CP_WAIT0();
    __syncthreads();

    // ---------- Q fragments into registers ----------
    float qf[8][4];
#pragma unroll
    for (int ks = 0; ks < 8; ks++) {
        const int kb = ks * 8;
        qf[ks][0] = sQ[(mr + g    ) * 68 + kb + t];
        qf[ks][1] = sQ[(mr + g + 8) * 68 + kb + t];
        qf[ks][2] = sQ[(mr + g    ) * 68 + kb + t + 4];
        qf[ks][3] = sQ[(mr + g + 8) * 68 + kb + t + 4];
    }

    // ---------- P[32][129] = Q @ table_k^T (interleaved 2-way + tail) ----------
    {
        float pacc[2][4];
#pragma unroll
        for (int j = 0; j < 2; j++)
#pragma unroll
            for (int r = 0; r < 4; r++) pacc[j][r] = 0.f;
#pragma unroll
        for (int ks = 0; ks < 8; ks++) {
            const int kb = ks * 8;
#pragma unroll
            for (int j = 0; j < 2; j++) {
                const int nb = (wg + 8 * j) * 8;
                float bb[2];
                bb[0] = sKV[(nb + g) * 68 + kb + t];
                bb[1] = sKV[(nb + g) * 68 + kb + t + 4];
                mma_tf32(pacc[j], qf[ks], bb);
            }
        }
#pragma unroll
        for (int j = 0; j < 2; j++) {
            const int nb = (wg + 8 * j) * 8;
            const int c0 = nb + 2 * t;
            sP[(mr + g    ) * 132 + c0]     = pacc[j][0];
            sP[(mr + g    ) * 132 + c0 + 1] = pacc[j][1];
            sP[(mr + g + 8) * 132 + c0]     = pacc[j][2];
            sP[(mr + g + 8) * 132 + c0 + 1] = pacc[j][3];
        }
        if (wg == 0) {
            float tacc[4] = {0.f, 0.f, 0.f, 0.f};
#pragma unroll
            for (int ks = 0; ks < 8; ks++) {
                const int kb = ks * 8;
                float bb[2];
                bb[0] = sKV[(128 + g) * 68 + kb + t];
                bb[1] = sKV[(128 + g) * 68 + kb + t + 4];
                mma_tf32(tacc, qf[ks], bb);
            }
            const int c0 = 128 + 2 * t;
            if (c0 < TAB) {
                sP[(mr + g    ) * 132 + c0] = tacc[0];
                sP[(mr + g + 8) * 132 + c0] = tacc[2];
            }
            if (c0 + 1 < TAB) {
                sP[(mr + g    ) * 132 + c0 + 1] = tacc[1];
                sP[(mr + g + 8) * 132 + c0 + 1] = tacc[3];
            }
        }
    }
    __syncthreads();   // table_k reads complete

    // ---------- issue K tile 0 ----------
#pragma unroll
    for (int j = 0; j < 4; j++) {
        const int idx = tid + 512 * j, row = idx >> 4, seg = idx & 15;
        CP_ASYNC16(sKVa + (uint32_t)(row * 68 + seg * 4) * 4,
                   gKb + (size_t)row * HID + seg * 4);
    }
    CP_COMMIT();

    // ---------- scores: 4 K-tiles of 128, double-buffered, 2-way ILP ----------
#pragma unroll 1
    for (int kt = 0; kt < 4; kt++) {
        if (kt < 3) {
            const uint32_t dstb = sKVa + (uint32_t)(((kt + 1) & 1) * 8704) * 4;
#pragma unroll
            for (int j = 0; j < 4; j++) {
                const int idx = tid + 512 * j, row = idx >> 4, seg = idx & 15;
                CP_ASYNC16(dstb + (uint32_t)(row * 68 + seg * 4) * 4,
                           gKb + (size_t)((kt + 1) * 128 + row) * HID + seg * 4);
            }
            CP_COMMIT();
            CP_WAIT1();
        } else {
            CP_WAIT0();
        }
        __syncthreads();

        const float* Kb = sKV + (kt & 1) * 8704;
        float sacc[2][4];
#pragma unroll
        for (int j = 0; j < 2; j++)
#pragma unroll
            for (int r = 0; r < 4; r++) sacc[j][r] = 0.f;

#pragma unroll
        for (int ks = 0; ks < 8; ks++) {
            const int kb = ks * 8;
#pragma unroll
            for (int jj = 0; jj < 2; jj++) {
                const int nb = (wg * 2 + jj) * 8;
                float bb[2];
                bb[0] = Kb[(nb + g) * 68 + kb + t];
                bb[1] = Kb[(nb + g) * 68 + kb + t + 4];
                mma_tf32(sacc[jj], qf[ks], bb);
            }
        }

#pragma unroll
        for (int jj = 0; jj < 2; jj++) {
            const int nb = (wg * 2 + jj) * 8;
            const int row0 = mr + g, row1 = row0 + 8;
            const int kc = kt * 128 + nb + 2 * t;
            const int t00 = sFb[row0 * 528 + kc], t01 = sFb[row0 * 528 + kc + 1];
            const int t10 = sFb[row1 * 528 + kc], t11 = sFb[row1 * 528 + kc + 1];
            sS[row0 * 516 + kc    ] = (sacc[jj][0] + sP[row0 * 132 + t00]) * 0.125f;
            sS[row0 * 516 + kc + 1] = (sacc[jj][1] + sP[row0 * 132 + t01]) * 0.125f;
            sS[row1 * 516 + kc    ] = (sacc[jj][2] + sP[row1 * 132 + t10]) * 0.125f;
            sS[row1 * 516 + kc + 1] = (sacc[jj][3] + sP[row1 * 132 + t11]) * 0.125f;
        }
        __syncthreads();
    }

    // ---------- issue V tile 0 (hides under softmax) ----------
#pragma unroll
    for (int j = 0; j < 4; j++) {
        const int idx = tid + 512 * j, row = idx >> 4, seg = idx & 15;
        CP_ASYNC16(sKVa + (uint32_t)(row * 72 + seg * 4) * 4,
                   gVb + (size_t)row * HID + seg * 4);
    }
    CP_COMMIT();

    // ---------- softmax (16 warps x 2 rows) ----------
    for (int r = warp * 2; r < warp * 2 + 2; r++) {
        float* row = sS + r * 516;
        float m = -1e30f;
#pragma unroll
        for (int i = 0; i < 16; i++) m = fmaxf(m, row[lane + 32 * i]);
#pragma unroll
        for (int o = 16; o > 0; o >>= 1) m = fmaxf(m, __shfl_xor_sync(0xffffffffu, m, o));
        float e[16];
        float s = 0.f;
#pragma unroll
        for (int i = 0; i < 16; i++) {
            e[i] = __expf(row[lane + 32 * i] - m);
            s += e[i];
        }
#pragma unroll
        for (int o = 16; o > 0; o >>= 1) s += __shfl_xor_sync(0xffffffffu, s, o);
        const float inv = 1.f / s;
#pragma unroll
        for (int i = 0; i < 16; i++) row[lane + 32 * i] = tf32r(e[i] * inv);
    }
    for (int i = tid; i < 32 * 136; i += 512) sSb[i] = 0.f;
    CP_WAIT0();
    __syncthreads();

    // ---------- w1 = attn @ V: 4 V-tiles of 128, dual accumulators ----------
    const int nbw = wg * 8;
    float acc1a[4] = {0.f, 0.f, 0.f, 0.f};
    float acc1b[4] = {0.f, 0.f, 0.f, 0.f};
#pragma unroll 1
    for (int vt = 0; vt < 4; vt++) {
        if (vt < 3) {
            const uint32_t dstb = sKVa + (uint32_t)(((vt + 1) & 1) * 9216) * 4;
#pragma unroll
            for (int j = 0; j < 4; j++) {
                const int idx = tid + 512 * j, row = idx >> 4, seg = idx & 15;
                CP_ASYNC16(dstb + (uint32_t)(row * 72 + seg * 4) * 4,
                           gVb + (size_t)((vt + 1) * 128 + row) * HID + seg * 4);
            }
            CP_COMMIT();
            CP_WAIT1();
        } else {
            CP_WAIT0();
        }
        __syncthreads();

        const float* Vb = sKV + (vt & 1) * 9216;
        const int cb = vt * 128;
#pragma unroll
        for (int ks = 0; ks < 16; ks += 2) {
            {
                const int kb = ks * 8;
                float a[4], bb[2];
                a[0] = sS[(mr + g    ) * 516 + cb + kb + t];
                a[1] = sS[(mr + g + 8) * 516 + cb + kb + t];
                a[2] = sS[(mr + g    ) * 516 + cb + kb + t + 4];
                a[3] = sS[(mr + g + 8) * 516 + cb + kb + t + 4];
                bb[0] = Vb[(kb + t    ) * 72 + nbw + g];
                bb[1] = Vb[(kb + t + 4) * 72 + nbw + g];
                mma_tf32(acc1a, a, bb);
            }
            {
                const int kb = (ks + 1) * 8;
                float a[4], bb[2];
                a[0] = sS[(mr + g    ) * 516 + cb + kb + t];
                a[1] = sS[(mr + g + 8) * 516 + cb + kb + t];
                a[2] = sS[(mr + g    ) * 516 + cb + kb + t + 4];
                a[3] = sS[(mr + g + 8) * 516 + cb + kb + t + 4];
                bb[0] = Vb[(kb + t    ) * 72 + nbw + g];
                bb[1] = Vb[(kb + t + 4) * 72 + nbw + g];
                mma_tf32(acc1b, a, bb);
            }
        }
        __syncthreads();
    }

    // ---------- bucket scatter (RED) + stage table_v ----------
    {
        const int q  = tid >> 4;
        const int kg = tid & 15;
        const unsigned char* fr = sFb + q * 528;
        const float* ar = sS + q * 516;
        float* sbq = sSb + q * 136;
#pragma unroll 4
        for (int i = 0; i < 32; i++) {
            const int k = i * 16 + kg;
            atomicAdd(&sbq[fr[k]], ar[k]);
        }
    }
    for (int i = tid; i < (136 * 72) / 4; i += 512)
        CP_ASYNC16(sKVa + (uint32_t)i * 16, g_tv + i * 4);
    CP_COMMIT();
    CP_WAIT0();
    __syncthreads();

    // ---------- w2 = buckets @ table_v (17 k-steps, dual accumulators) ----------
    float acc2a[4] = {0.f, 0.f, 0.f, 0.f};
    float acc2b[4] = {0.f, 0.f, 0.f, 0.f};
#pragma unroll
    for (int ks = 0; ks < 17; ks++) {
        const int kb = ks * 8;
        float a[4], bb[2];
        a[0] = tf32r(sSb[(mr + g    ) * 136 + kb + t]);
        a[1] = tf32r(sSb[(mr + g + 8) * 136 + kb + t]);
        a[2] = tf32r(sSb[(mr + g    ) * 136 + kb + t + 4]);
        a[3] = tf32r(sSb[(mr + g + 8) * 136 + kb + t + 4]);
        bb[0] = sKV[(kb + t    ) * 72 + nbw + g];
        bb[1] = sKV[(kb + t + 4) * 72 + nbw + g];
        if (ks & 1) mma_tf32(acc2b, a, bb);
        else        mma_tf32(acc2a, a, bb);
    }

    // ---------- store (tf32-rounded for gemm_out's cp.async A path) ----------
    {
        const int row0 = mr + g;
        const int col  = nbw + 2 * t;
        float2 o0 = make_float2(tf32r(acc1a[0] + acc1b[0] + acc2a[0] + acc2b[0]),
                                tf32r(acc1a[1] + acc1b[1] + acc2a[1] + acc2b[1]));
        float2 o1 = make_float2(tf32r(acc1a[2] + acc1b[2] + acc2a[2] + acc2b[2]),
                                tf32r(acc1a[3] + acc1b[3] + acc2a[3] + acc2b[3]));
        *reinterpret_cast<float2*>(
            g_X + (size_t)(b * L + q0 + row0) * HID + h * HD + col) = o0;
        *reinterpret_cast<float2*>(
            g_X + (size_t)(b * L + q0 + row0 + 8) * HID + h * HD + col) = o1;
    }
}

// =====================================================================
// launch
// =====================================================================
extern "C" void kernel_launch(void* const* d_in, const int* in_sizes, int n_in,
                              void* d_out, int out_size)
{
    const float* query   = (const float*)d_in[0];
    const float* key     = (const float*)d_in[1];
    const float* value   = (const float*)d_in[2];
    const int*   fm      = (const int*)  d_in[3];
    const float* Wq      = (const float*)d_in[4];
    const float* bq      = (const float*)d_in[5];
    const float* Wk      = (const float*)d_in[6];
    const float* bk      = (const float*)d_in[7];
    const float* Wv      = (const float*)d_in[8];
    const float* bv      = (const float*)d_in[9];
    const float* Wo      = (const float*)d_in[10];
    const float* bo      = (const float*)d_in[11];
    const float* table_k = (const float*)d_in[12];
    const float* table_v = (const float*)d_in[13];
    float* out = (float*)d_out;

    cudaFuncSetAttribute(attn_fused_mma,
                         cudaFuncAttributeMaxDynamicSharedMemorySize, (int)SMF_BYTES);
    cudaFuncSetAttribute(gemm_qkv,
                         cudaFuncAttributeMaxDynamicSharedMemorySize, (int)GEMM_SMEM);
    cudaFuncSetAttribute(gemm_out,
                         cudaFuncAttributeMaxDynamicSharedMemorySize, (int)GEMM_SMEM);

    prep_kernel<<<2049 + 4096, 256>>>(fm, table_k, table_v, Wq, Wk, Wv, Wo);

    const dim3 gqkv(HID / 128, BL / 128, 3);  // (8, 32, 3) = 768 blocks
    gemm_qkv<<<gqkv, 256, GEMM_SMEM>>>(query, key, value, bq, bk, bv);

    const dim3 gattn(L / 32, H, B);  // (16, 16, 8)
    attn_fused_mma<<<gattn, 512, SMF_BYTES>>>();

    const dim3 gout(HID / 128, BL / 128);  // (8, 32) = 256 blocks
    gemm_out<<<gout, 256, GEMM_SMEM>>>(bo, out);
}